// round 10
// baseline (speedup 1.0000x reference)
#include <cuda_runtime.h>
#include <cuda_bf16.h>
#include <cstdint>

#define LQ 43054
#define D  256
#define NH 8
#define NL 4
#define NP 4
#define HD 32

// ---------------- scratch (device globals) ----------------
__device__ __nv_bfloat16 g_valh[LQ * D];
__device__ float g_ol  [LQ * 384];       // [0:256)=offsets, [256:384)=logits
__device__ float g_acc [LQ * D];
__device__ float g_x   [LQ * D];
__device__ float g_h   [LQ * D];
__device__ float g_f   [LQ * D];
__device__ float g_wcat[256 * 384];
__device__ float g_bcat[384];

// ---------------- weight pack: [w_off | w_attn] ----------------
__global__ void pack_w(const float* __restrict__ w_off, const float* __restrict__ b_off,
                       const float* __restrict__ w_attn, const float* __restrict__ b_attn,
                       float* __restrict__ wcat, float* __restrict__ bcat) {
    int i = blockIdx.x * blockDim.x + threadIdx.x;
    if (i >= 256 * 384) return;
    int k = i / 384, n = i % 384;
    wcat[i] = (n < 256) ? w_off[k * 256 + n] : w_attn[k * 128 + (n - 256)];
    if (i < 384) bcat[i] = (i < 256) ? b_off[i] : b_attn[i - 256];
}

// ---------------- bf16 tensor-core GEMM, BM=64 BN=64 BK=64 ----------------
// C[M,N] = (A [+ A2])[M,256] @ B[256,N] + bias. 128 thr = 4 warps (2x2),
// warp tile 32x32; mma.m16n8k16.bf16, fp32 accum.
// mode: 0 = fp32 out, 1 = fp32+ReLU, 2 = bf16 out
__global__ __launch_bounds__(128, 6)
void tgemm(const float* __restrict__ A, const float* __restrict__ A2,
           const float* __restrict__ B,
           const float* __restrict__ bias, void* __restrict__ Cv,
           int M, int N, int mode) {
    constexpr int K = 256;
    constexpr int LDA = 72;
    constexpr int LDB = 72;
    __shared__ __align__(16) __nv_bfloat16 As[64 * LDA];
    __shared__ __align__(16) __nv_bfloat16 Bs[64 * LDB];

    int tid = threadIdx.x;
    int lane = tid & 31;
    int wid = tid >> 5;
    int bm = blockIdx.y * 64;
    int bn = blockIdx.x * 64;
    int wm = (wid >> 1) * 32;
    int wn = (wid & 1) * 32;

    float c[2][4][4];
    #pragma unroll
    for (int i = 0; i < 2; i++)
        #pragma unroll
        for (int j = 0; j < 4; j++)
            #pragma unroll
            for (int r = 0; r < 4; r++) c[i][j][r] = 0.f;

    int a_row = lane & 15;
    int a_koff = (lane >> 4) * 8;
    int b_krow = (lane & 7) + ((lane >> 3) & 1) * 8;
    int b_noff = (lane >> 4) * 8;

    for (int k0 = 0; k0 < K; k0 += 64) {
        // stage A: 64 rows x 64 k (f32 -> bf16)
        #pragma unroll
        for (int i = 0; i < 8; i++) {
            int slot = tid + i * 128;
            int row = slot >> 4;
            int k4 = (slot & 15) * 4;
            float4 v = make_float4(0.f, 0.f, 0.f, 0.f);
            if (bm + row < M) {
                v = *reinterpret_cast<const float4*>(A + (size_t)(bm + row) * K + k0 + k4);
                if (A2) {
                    float4 u = *reinterpret_cast<const float4*>(A2 + (size_t)(bm + row) * K + k0 + k4);
                    v.x += u.x; v.y += u.y; v.z += u.z; v.w += u.w;
                }
            }
            __nv_bfloat162 p0 = __floats2bfloat162_rn(v.x, v.y);
            __nv_bfloat162 p1 = __floats2bfloat162_rn(v.z, v.w);
            uint2 st;
            st.x = *reinterpret_cast<uint32_t*>(&p0);
            st.y = *reinterpret_cast<uint32_t*>(&p1);
            *reinterpret_cast<uint2*>(&As[row * LDA + k4]) = st;
        }
        // stage B: 64 k-rows x 64 n (f32 -> bf16)
        #pragma unroll
        for (int i = 0; i < 8; i++) {
            int slot = tid + i * 128;
            int kk = slot >> 4;
            int n4 = (slot & 15) * 4;
            float4 v = *reinterpret_cast<const float4*>(B + (size_t)(k0 + kk) * N + bn + n4);
            __nv_bfloat162 p0 = __floats2bfloat162_rn(v.x, v.y);
            __nv_bfloat162 p1 = __floats2bfloat162_rn(v.z, v.w);
            uint2 st;
            st.x = *reinterpret_cast<uint32_t*>(&p0);
            st.y = *reinterpret_cast<uint32_t*>(&p1);
            *reinterpret_cast<uint2*>(&Bs[kk * LDB + n4]) = st;
        }
        __syncthreads();

        #pragma unroll
        for (int ks = 0; ks < 4; ks++) {
            int kbase = ks * 16;
            uint32_t af[2][4];
            #pragma unroll
            for (int mf = 0; mf < 2; mf++) {
                const __nv_bfloat16* p = &As[(wm + mf * 16 + a_row) * LDA + kbase + a_koff];
                uint32_t addr = (uint32_t)__cvta_generic_to_shared(p);
                asm volatile("ldmatrix.sync.aligned.m8n8.x4.shared.b16 {%0,%1,%2,%3}, [%4];"
                             : "=r"(af[mf][0]), "=r"(af[mf][1]), "=r"(af[mf][2]), "=r"(af[mf][3])
                             : "r"(addr));
            }
            uint32_t bf[4][2];
            #pragma unroll
            for (int n16 = 0; n16 < 2; n16++) {
                const __nv_bfloat16* p = &Bs[(kbase + b_krow) * LDB + wn + n16 * 16 + b_noff];
                uint32_t addr = (uint32_t)__cvta_generic_to_shared(p);
                asm volatile("ldmatrix.sync.aligned.m8n8.x4.trans.shared.b16 {%0,%1,%2,%3}, [%4];"
                             : "=r"(bf[n16 * 2][0]), "=r"(bf[n16 * 2][1]),
                               "=r"(bf[n16 * 2 + 1][0]), "=r"(bf[n16 * 2 + 1][1])
                             : "r"(addr));
            }
            #pragma unroll
            for (int mf = 0; mf < 2; mf++)
                #pragma unroll
                for (int nf = 0; nf < 4; nf++) {
                    asm volatile(
                        "mma.sync.aligned.m16n8k16.row.col.f32.bf16.bf16.f32 "
                        "{%0,%1,%2,%3}, {%4,%5,%6,%7}, {%8,%9}, {%0,%1,%2,%3};"
                        : "+f"(c[mf][nf][0]), "+f"(c[mf][nf][1]),
                          "+f"(c[mf][nf][2]), "+f"(c[mf][nf][3])
                        : "r"(af[mf][0]), "r"(af[mf][1]), "r"(af[mf][2]), "r"(af[mf][3]),
                          "r"(bf[nf][0]), "r"(bf[nf][1]));
                }
        }
        __syncthreads();
    }

    #pragma unroll
    for (int mf = 0; mf < 2; mf++) {
        int row0 = bm + wm + mf * 16 + (lane >> 2);
        #pragma unroll
        for (int nf = 0; nf < 4; nf++) {
            int col = bn + wn + nf * 8 + (lane & 3) * 2;
            float bx = bias[col], by = bias[col + 1];
            float2 v0, v1;
            v0.x = c[mf][nf][0] + bx; v0.y = c[mf][nf][1] + by;
            v1.x = c[mf][nf][2] + bx; v1.y = c[mf][nf][3] + by;
            if (mode == 1) {
                v0.x = fmaxf(v0.x, 0.f); v0.y = fmaxf(v0.y, 0.f);
                v1.x = fmaxf(v1.x, 0.f); v1.y = fmaxf(v1.y, 0.f);
            }
            if (mode == 2) {
                __nv_bfloat16* C = (__nv_bfloat16*)Cv;
                if (row0 < M)
                    *reinterpret_cast<__nv_bfloat162*>(C + (size_t)row0 * N + col) =
                        __floats2bfloat162_rn(v0.x, v0.y);
                if (row0 + 8 < M)
                    *reinterpret_cast<__nv_bfloat162*>(C + (size_t)(row0 + 8) * N + col) =
                        __floats2bfloat162_rn(v1.x, v1.y);
            } else {
                float* C = (float*)Cv;
                if (row0 < M)
                    *reinterpret_cast<float2*>(C + (size_t)row0 * N + col) = v0;
                if (row0 + 8 < M)
                    *reinterpret_cast<float2*>(C + (size_t)(row0 + 8) * N + col) = v1;
            }
        }
    }
}

// ---------------- deformable sampling ----------
__global__ __launch_bounds__(256)
void sample_kernel(const __nv_bfloat16* __restrict__ valh,
                   const float* __restrict__ refp,
                   const float* __restrict__ ol,     // (LQ, 384): off | logits
                   const int* __restrict__ shapes,
                   const int* __restrict__ starts,
                   float* __restrict__ acc) {
    __shared__ float aw_s[NH * 16];
    __shared__ __align__(16) int2 pw_s[512];

    int lq = blockIdx.x;
    int tid = threadIdx.x;
    int h = tid >> 5;
    int lane = tid & 31;
    const unsigned FULL = 0xffffffffu;

    // ---- phase 0: softmax per head ----
    {
        const float* lg = ol + (size_t)lq * 384 + 256 + h * 16;
        float myl = (lane < 16) ? lg[lane] : -1e30f;
        float mx = myl;
        #pragma unroll
        for (int o = 8; o; o >>= 1) mx = fmaxf(mx, __shfl_xor_sync(FULL, mx, o));
        float e = (lane < 16) ? __expf(myl - mx) : 0.f;
        float sum = e;
        #pragma unroll
        for (int o = 16; o; o >>= 1) sum += __shfl_xor_sync(FULL, sum, o);
        float inv = 1.f / sum;
        if (lane < 16) aw_s[h * 16 + lane] = e * inv;
    }
    __syncthreads();

    // ---- phase 1: one POINT per thread (tid < 128), emit 4 corners ----
    if (tid < 128) {
        int jh = tid >> 4;
        int p = tid & 15;
        int l = p >> 2;

        int Hl = __ldg(&shapes[l * 2 + 0]);
        int Wl = __ldg(&shapes[l * 2 + 1]);
        int st = __ldg(&starts[l]);
        float fW = (float)Wl, fH = (float)Hl;

        float rx = __ldg(&refp[(size_t)lq * 8 + l * 2 + 0]);
        float ry = __ldg(&refp[(size_t)lq * 8 + l * 2 + 1]);
        float2 oxy = __ldg(reinterpret_cast<const float2*>(ol + (size_t)lq * 384 + jh * 32 + p * 2));

        float x = rx * fW + oxy.x - 0.5f;
        float y = ry * fH + oxy.y - 0.5f;
        float x0f = floorf(x), y0f = floorf(y);
        float fx = x - x0f, fy = y - y0f;
        int x0 = (int)x0f, y0 = (int)y0f;
        float aw = aw_s[jh * 16 + p];

        float wx1 = fx * aw, wx0 = aw - wx1;
        float w00 = wx0 * (1.f - fy), w01 = wx1 * (1.f - fy);
        float w10 = wx0 * fy,         w11 = wx1 * fy;

        bool vx0 = (unsigned)x0 < (unsigned)Wl;
        bool vx1 = (unsigned)(x0 + 1) < (unsigned)Wl;
        bool vy0 = (unsigned)y0 < (unsigned)Hl;
        bool vy1 = (unsigned)(y0 + 1) < (unsigned)Hl;
        if (!(vx0 && vy0)) w00 = 0.f;
        if (!(vx1 && vy0)) w01 = 0.f;
        if (!(vx0 && vy1)) w10 = 0.f;
        if (!(vx1 && vy1)) w11 = 0.f;

        int xc0 = min(max(x0, 0), Wl - 1);
        int xc1 = min(max(x0 + 1, 0), Wl - 1);
        int yc0 = min(max(y0, 0), Hl - 1);
        int yc1 = min(max(y0 + 1, 0), Hl - 1);
        int base = st * 512 + jh * 64;
        int r0 = yc0 * Wl, r1 = yc1 * Wl;

        int4 e0, e1;
        e0.x = base + (r0 + xc0) * 512; e0.y = __float_as_int(w00);
        e0.z = base + (r0 + xc1) * 512; e0.w = __float_as_int(w01);
        e1.x = base + (r1 + xc0) * 512; e1.y = __float_as_int(w10);
        e1.z = base + (r1 + xc1) * 512; e1.w = __float_as_int(w11);
        int4* dst = reinterpret_cast<int4*>(&pw_s[tid * 4]);
        dst[0] = e0;
        dst[1] = e1;
    }
    __syncthreads();

    // ---- phase 2: 8 corners per LDG.128 round ----
    {
        const int2* pw = pw_s + h * 64;
        int cor = lane >> 2;
        int ch = lane & 3;
        const char* vbase = reinterpret_cast<const char*>(valh) + 16 * ch;
        int2 q[8];
        #pragma unroll
        for (int i = 0; i < 8; i++) q[i] = pw[i * 8 + cor];
        float a[8];
        #pragma unroll
        for (int i = 0; i < 8; i++) a[i] = 0.f;
        #pragma unroll
        for (int i = 0; i < 8; i++) {
            float w = __int_as_float(q[i].y);
            uint4 v = *reinterpret_cast<const uint4*>(vbase + q[i].x);
            float2 f0 = __bfloat1622float2(*reinterpret_cast<__nv_bfloat162*>(&v.x));
            float2 f1 = __bfloat1622float2(*reinterpret_cast<__nv_bfloat162*>(&v.y));
            float2 f2 = __bfloat1622float2(*reinterpret_cast<__nv_bfloat162*>(&v.z));
            float2 f3 = __bfloat1622float2(*reinterpret_cast<__nv_bfloat162*>(&v.w));
            a[0] += w * f0.x; a[1] += w * f0.y;
            a[2] += w * f1.x; a[3] += w * f1.y;
            a[4] += w * f2.x; a[5] += w * f2.y;
            a[6] += w * f3.x; a[7] += w * f3.y;
        }
        #pragma unroll
        for (int o = 4; o <= 16; o <<= 1)
            #pragma unroll
            for (int i = 0; i < 8; i++)
                a[i] += __shfl_xor_sync(FULL, a[i], o);
        if (lane < 4) {
            float* dst = acc + (size_t)lq * 256 + h * 32 + 8 * ch;
            float4 o0; o0.x = a[0]; o0.y = a[1]; o0.z = a[2]; o0.w = a[3];
            float4 o1; o1.x = a[4]; o1.y = a[5]; o1.z = a[6]; o1.w = a[7];
            *reinterpret_cast<float4*>(dst) = o0;
            *reinterpret_cast<float4*>(dst + 4) = o1;
        }
    }
}

// ---------------- fused residual + LayerNorm (warp per row) ----------------
__global__ __launch_bounds__(256)
void ln_kernel(const float* __restrict__ res, const float* __restrict__ y,
               const float* __restrict__ g, const float* __restrict__ b,
               float* __restrict__ out, int M) {
    int warp = (blockIdx.x * blockDim.x + threadIdx.x) >> 5;
    int lane = threadIdx.x & 31;
    if (warp >= M) return;
    const float* r  = res + (size_t)warp * 256;
    const float* yy = y   + (size_t)warp * 256;
    float v[8];
    float s = 0.f;
    #pragma unroll
    for (int i = 0; i < 8; i++) {
        v[i] = __ldg(r + lane + 32 * i) + __ldg(yy + lane + 32 * i);
        s += v[i];
    }
    #pragma unroll
    for (int o = 16; o; o >>= 1) s += __shfl_xor_sync(0xffffffffu, s, o);
    float m = s * (1.f / 256.f);
    float vs = 0.f;
    #pragma unroll
    for (int i = 0; i < 8; i++) { float d = v[i] - m; vs += d * d; }
    #pragma unroll
    for (int o = 16; o; o >>= 1) vs += __shfl_xor_sync(0xffffffffu, vs, o);
    float rs = rsqrtf(vs * (1.f / 256.f) + 1e-5f);
    #pragma unroll
    for (int i = 0; i < 8; i++) {
        int c = lane + 32 * i;
        out[(size_t)warp * 256 + c] = (v[i] - m) * rs * __ldg(g + c) + __ldg(b + c);
    }
}

// ---------------- host ----------------
extern "C" void kernel_launch(void* const* d_in, const int* in_sizes, int n_in,
                              void* d_out, int out_size) {
    const float* query = (const float*)d_in[0];
    const float* refp  = (const float*)d_in[1];
    const float* pos   = (const float*)d_in[2];
    const int*   shp   = (const int*)d_in[3];
    const int*   sti   = (const int*)d_in[4];
    const float* w_off = (const float*)d_in[5];
    const float* b_off = (const float*)d_in[6];
    const float* w_attn= (const float*)d_in[7];
    const float* b_attn= (const float*)d_in[8];
    const float* w_val = (const float*)d_in[9];
    const float* b_val = (const float*)d_in[10];
    const float* w_out = (const float*)d_in[11];
    const float* b_out = (const float*)d_in[12];
    const float* g1    = (const float*)d_in[13];
    const float* be1   = (const float*)d_in[14];
    const float* w1    = (const float*)d_in[15];
    const float* b1    = (const float*)d_in[16];
    const float* w2    = (const float*)d_in[17];
    const float* b2    = (const float*)d_in[18];
    const float* g2    = (const float*)d_in[19];
    const float* be2   = (const float*)d_in[20];
    float* out = (float*)d_out;

    float *ol, *acc, *x, *h, *f, *wcat, *bcat;
    __nv_bfloat16* valh;
    cudaGetSymbolAddress((void**)&valh, g_valh);
    cudaGetSymbolAddress((void**)&ol,   g_ol);
    cudaGetSymbolAddress((void**)&acc,  g_acc);
    cudaGetSymbolAddress((void**)&x,    g_x);
    cudaGetSymbolAddress((void**)&h,    g_h);
    cudaGetSymbolAddress((void**)&f,    g_f);
    cudaGetSymbolAddress((void**)&wcat, g_wcat);
    cudaGetSymbolAddress((void**)&bcat, g_bcat);

    const int M = LQ;
    const int mt = (M + 63) / 64;          // 673
    dim3 grid_n256(4, mt);
    dim3 grid_n384(6, mt);

    cudaStream_t s1;
    cudaStreamCreateWithFlags(&s1, cudaStreamNonBlocking);
    cudaEvent_t e0, e1;
    cudaEventCreateWithFlags(&e0, cudaEventDisableTiming);
    cudaEventCreateWithFlags(&e1, cudaEventDisableTiming);

    cudaEventRecord(e0, 0);
    cudaStreamWaitEvent(s1, e0, 0);
    tgemm<<<grid_n256, 128, 0, s1>>>(query, nullptr, w_val, b_val, valh, M, 256, 2);

    pack_w<<<(256 * 384 + 255) / 256, 256>>>(w_off, b_off, w_attn, b_attn, wcat, bcat);
    tgemm<<<grid_n384, 128>>>(query, pos, wcat, bcat, ol, M, 384, 0);

    cudaEventRecord(e1, s1);
    cudaStreamWaitEvent(0, e1, 0);

    sample_kernel<<<LQ, 256>>>(valh, refp, ol, shp, sti, acc);
    tgemm<<<grid_n256, 128>>>(acc, nullptr, w_out, b_out, f, M, 256, 0);
    {
        int blocks = (M * 32 + 255) / 256;
        ln_kernel<<<blocks, 256>>>(query, f, g1, be1, x, M);
    }
    tgemm<<<grid_n256, 128>>>(x, nullptr, w1, b1, h, M, 256, 1);
    tgemm<<<grid_n256, 128>>>(h, nullptr, w2, b2, f, M, 256, 0);
    {
        int blocks = (M * 32 + 255) / 256;
        ln_kernel<<<blocks, 256>>>(x, f, g2, be2, out, M);
    }
}

// round 11
// speedup vs baseline: 1.0955x; 1.0955x over previous
#include <cuda_runtime.h>
#include <cuda_bf16.h>
#include <cstdint>

#define LQ 43054
#define D  256
#define NH 8
#define NL 4
#define NP 4
#define HD 32

// ---------------- scratch (device globals) ----------------
__device__ __nv_bfloat16 g_valh[LQ * D];
__device__ float g_ol  [LQ * 384];       // [0:256)=offsets, [256:384)=logits
__device__ float g_acc [LQ * D];
__device__ float g_x   [LQ * D];
__device__ float g_h   [LQ * D];
__device__ float g_wcat[256 * 384];
__device__ float g_bcat[384];

// ---------------- weight pack: [w_off | w_attn] ----------------
__global__ void pack_w(const float* __restrict__ w_off, const float* __restrict__ b_off,
                       const float* __restrict__ w_attn, const float* __restrict__ b_attn,
                       float* __restrict__ wcat, float* __restrict__ bcat) {
    int i = blockIdx.x * blockDim.x + threadIdx.x;
    if (i >= 256 * 384) return;
    int k = i / 384, n = i % 384;
    wcat[i] = (n < 256) ? w_off[k * 256 + n] : w_attn[k * 128 + (n - 256)];
    if (i < 384) bcat[i] = (i < 256) ? b_off[i] : b_attn[i - 256];
}

// ---------------- bf16 tensor-core GEMM (R9 config: BM=128 BN=128 BK=64) ----
// mode: 0 = fp32 out, 1 = fp32+ReLU, 2 = bf16 out
__global__ __launch_bounds__(256, 2)
void tgemm(const float* __restrict__ A, const float* __restrict__ A2,
           const float* __restrict__ B,
           const float* __restrict__ bias, void* __restrict__ Cv,
           int M, int N, int mode) {
    constexpr int K = 256;
    constexpr int LDA = 72;
    constexpr int LDB = 136;
    __shared__ __align__(16) __nv_bfloat16 As[128 * LDA];
    __shared__ __align__(16) __nv_bfloat16 Bs[64 * LDB];

    int tid = threadIdx.x;
    int lane = tid & 31;
    int wid = tid >> 5;
    int bm = blockIdx.y * 128;
    int bn = blockIdx.x * 128;
    int wm = (wid >> 2) * 64;
    int wn = (wid & 3) * 32;

    float c[4][4][4];
    #pragma unroll
    for (int i = 0; i < 4; i++)
        #pragma unroll
        for (int j = 0; j < 4; j++)
            #pragma unroll
            for (int r = 0; r < 4; r++) c[i][j][r] = 0.f;

    int a_row = lane & 15;
    int a_koff = (lane >> 4) * 8;
    int b_krow = (lane & 7) + ((lane >> 3) & 1) * 8;
    int b_noff = (lane >> 4) * 8;

    for (int k0 = 0; k0 < K; k0 += 64) {
        #pragma unroll
        for (int i = 0; i < 8; i++) {
            int slot = tid + i * 256;
            int row = slot >> 4;
            int k4 = (slot & 15) * 4;
            float4 v = make_float4(0.f, 0.f, 0.f, 0.f);
            if (bm + row < M) {
                v = *reinterpret_cast<const float4*>(A + (size_t)(bm + row) * K + k0 + k4);
                if (A2) {
                    float4 u = *reinterpret_cast<const float4*>(A2 + (size_t)(bm + row) * K + k0 + k4);
                    v.x += u.x; v.y += u.y; v.z += u.z; v.w += u.w;
                }
            }
            __nv_bfloat162 p0 = __floats2bfloat162_rn(v.x, v.y);
            __nv_bfloat162 p1 = __floats2bfloat162_rn(v.z, v.w);
            uint2 st;
            st.x = *reinterpret_cast<uint32_t*>(&p0);
            st.y = *reinterpret_cast<uint32_t*>(&p1);
            *reinterpret_cast<uint2*>(&As[row * LDA + k4]) = st;
        }
        #pragma unroll
        for (int i = 0; i < 8; i++) {
            int slot = tid + i * 256;
            int kk = slot >> 5;
            int n4 = (slot & 31) * 4;
            float4 v = *reinterpret_cast<const float4*>(B + (size_t)(k0 + kk) * N + bn + n4);
            __nv_bfloat162 p0 = __floats2bfloat162_rn(v.x, v.y);
            __nv_bfloat162 p1 = __floats2bfloat162_rn(v.z, v.w);
            uint2 st;
            st.x = *reinterpret_cast<uint32_t*>(&p0);
            st.y = *reinterpret_cast<uint32_t*>(&p1);
            *reinterpret_cast<uint2*>(&Bs[kk * LDB + n4]) = st;
        }
        __syncthreads();

        #pragma unroll
        for (int ks = 0; ks < 4; ks++) {
            int kbase = ks * 16;
            uint32_t af[4][4];
            #pragma unroll
            for (int mf = 0; mf < 4; mf++) {
                const __nv_bfloat16* p = &As[(wm + mf * 16 + a_row) * LDA + kbase + a_koff];
                uint32_t addr = (uint32_t)__cvta_generic_to_shared(p);
                asm volatile("ldmatrix.sync.aligned.m8n8.x4.shared.b16 {%0,%1,%2,%3}, [%4];"
                             : "=r"(af[mf][0]), "=r"(af[mf][1]), "=r"(af[mf][2]), "=r"(af[mf][3])
                             : "r"(addr));
            }
            uint32_t bf[4][2];
            #pragma unroll
            for (int n16 = 0; n16 < 2; n16++) {
                const __nv_bfloat16* p = &Bs[(kbase + b_krow) * LDB + wn + n16 * 16 + b_noff];
                uint32_t addr = (uint32_t)__cvta_generic_to_shared(p);
                asm volatile("ldmatrix.sync.aligned.m8n8.x4.trans.shared.b16 {%0,%1,%2,%3}, [%4];"
                             : "=r"(bf[n16 * 2][0]), "=r"(bf[n16 * 2][1]),
                               "=r"(bf[n16 * 2 + 1][0]), "=r"(bf[n16 * 2 + 1][1])
                             : "r"(addr));
            }
            #pragma unroll
            for (int mf = 0; mf < 4; mf++)
                #pragma unroll
                for (int nf = 0; nf < 4; nf++) {
                    asm volatile(
                        "mma.sync.aligned.m16n8k16.row.col.f32.bf16.bf16.f32 "
                        "{%0,%1,%2,%3}, {%4,%5,%6,%7}, {%8,%9}, {%0,%1,%2,%3};"
                        : "+f"(c[mf][nf][0]), "+f"(c[mf][nf][1]),
                          "+f"(c[mf][nf][2]), "+f"(c[mf][nf][3])
                        : "r"(af[mf][0]), "r"(af[mf][1]), "r"(af[mf][2]), "r"(af[mf][3]),
                          "r"(bf[nf][0]), "r"(bf[nf][1]));
                }
        }
        __syncthreads();
    }

    #pragma unroll
    for (int mf = 0; mf < 4; mf++) {
        int row0 = bm + wm + mf * 16 + (lane >> 2);
        #pragma unroll
        for (int nf = 0; nf < 4; nf++) {
            int col = bn + wn + nf * 8 + (lane & 3) * 2;
            float bx = bias[col], by = bias[col + 1];
            float2 v0, v1;
            v0.x = c[mf][nf][0] + bx; v0.y = c[mf][nf][1] + by;
            v1.x = c[mf][nf][2] + bx; v1.y = c[mf][nf][3] + by;
            if (mode == 1) {
                v0.x = fmaxf(v0.x, 0.f); v0.y = fmaxf(v0.y, 0.f);
                v1.x = fmaxf(v1.x, 0.f); v1.y = fmaxf(v1.y, 0.f);
            }
            if (mode == 2) {
                __nv_bfloat16* C = (__nv_bfloat16*)Cv;
                if (row0 < M)
                    *reinterpret_cast<__nv_bfloat162*>(C + (size_t)row0 * N + col) =
                        __floats2bfloat162_rn(v0.x, v0.y);
                if (row0 + 8 < M)
                    *reinterpret_cast<__nv_bfloat162*>(C + (size_t)(row0 + 8) * N + col) =
                        __floats2bfloat162_rn(v1.x, v1.y);
            } else {
                float* C = (float*)Cv;
                if (row0 < M)
                    *reinterpret_cast<float2*>(C + (size_t)row0 * N + col) = v0;
                if (row0 + 8 < M)
                    *reinterpret_cast<float2*>(C + (size_t)(row0 + 8) * N + col) = v1;
            }
        }
    }
}

// ---------------- bf16 GEMM + residual + LayerNorm fused ----------------
// out[M,256] = LN(res + A@B + bias) * gam + bet.  BM=64, BN=256 (full row),
// 256 threads = 8 warps (2x4); warp tile 32x64.
__global__ __launch_bounds__(256)
void tgemm_ln(const float* __restrict__ A, const float* __restrict__ B,
              const float* __restrict__ bias, const float* __restrict__ res,
              const float* __restrict__ gam, const float* __restrict__ bet,
              float* __restrict__ out, int M) {
    constexpr int K = 256;
    constexpr int N = 256;
    constexpr int LDA = 72;
    constexpr int LDB = 264;
    __shared__ __align__(16) __nv_bfloat16 As[64 * LDA];
    __shared__ __align__(16) __nv_bfloat16 Bs[64 * LDB];
    __shared__ float rsum[4][64];
    __shared__ float rsq[4][64];

    int tid = threadIdx.x;
    int lane = tid & 31;
    int wid = tid >> 5;
    int bm = blockIdx.x * 64;
    int wm = (wid >> 2) * 32;
    int wn = (wid & 3) * 64;

    float c[2][8][4];
    #pragma unroll
    for (int i = 0; i < 2; i++)
        #pragma unroll
        for (int j = 0; j < 8; j++)
            #pragma unroll
            for (int r = 0; r < 4; r++) c[i][j][r] = 0.f;

    int a_row = lane & 15;
    int a_koff = (lane >> 4) * 8;
    int b_krow = (lane & 7) + ((lane >> 3) & 1) * 8;
    int b_noff = (lane >> 4) * 8;

    for (int k0 = 0; k0 < K; k0 += 64) {
        // stage A: 64 rows x 64 k
        #pragma unroll
        for (int i = 0; i < 4; i++) {
            int slot = tid + i * 256;
            int row = slot >> 4;
            int k4 = (slot & 15) * 4;
            float4 v = make_float4(0.f, 0.f, 0.f, 0.f);
            if (bm + row < M)
                v = *reinterpret_cast<const float4*>(A + (size_t)(bm + row) * K + k0 + k4);
            __nv_bfloat162 p0 = __floats2bfloat162_rn(v.x, v.y);
            __nv_bfloat162 p1 = __floats2bfloat162_rn(v.z, v.w);
            uint2 st;
            st.x = *reinterpret_cast<uint32_t*>(&p0);
            st.y = *reinterpret_cast<uint32_t*>(&p1);
            *reinterpret_cast<uint2*>(&As[row * LDA + k4]) = st;
        }
        // stage B: 64 k-rows x 256 n
        #pragma unroll
        for (int i = 0; i < 16; i++) {
            int slot = tid + i * 256;
            int kk = slot >> 6;
            int n4 = (slot & 63) * 4;
            float4 v = *reinterpret_cast<const float4*>(B + (size_t)(k0 + kk) * N + n4);
            __nv_bfloat162 p0 = __floats2bfloat162_rn(v.x, v.y);
            __nv_bfloat162 p1 = __floats2bfloat162_rn(v.z, v.w);
            uint2 st;
            st.x = *reinterpret_cast<uint32_t*>(&p0);
            st.y = *reinterpret_cast<uint32_t*>(&p1);
            *reinterpret_cast<uint2*>(&Bs[kk * LDB + n4]) = st;
        }
        __syncthreads();

        #pragma unroll
        for (int ks = 0; ks < 4; ks++) {
            int kbase = ks * 16;
            uint32_t af[2][4];
            #pragma unroll
            for (int mf = 0; mf < 2; mf++) {
                const __nv_bfloat16* p = &As[(wm + mf * 16 + a_row) * LDA + kbase + a_koff];
                uint32_t addr = (uint32_t)__cvta_generic_to_shared(p);
                asm volatile("ldmatrix.sync.aligned.m8n8.x4.shared.b16 {%0,%1,%2,%3}, [%4];"
                             : "=r"(af[mf][0]), "=r"(af[mf][1]), "=r"(af[mf][2]), "=r"(af[mf][3])
                             : "r"(addr));
            }
            uint32_t bf[8][2];
            #pragma unroll
            for (int n16 = 0; n16 < 4; n16++) {
                const __nv_bfloat16* p = &Bs[(kbase + b_krow) * LDB + wn + n16 * 16 + b_noff];
                uint32_t addr = (uint32_t)__cvta_generic_to_shared(p);
                asm volatile("ldmatrix.sync.aligned.m8n8.x4.trans.shared.b16 {%0,%1,%2,%3}, [%4];"
                             : "=r"(bf[n16 * 2][0]), "=r"(bf[n16 * 2][1]),
                               "=r"(bf[n16 * 2 + 1][0]), "=r"(bf[n16 * 2 + 1][1])
                             : "r"(addr));
            }
            #pragma unroll
            for (int mf = 0; mf < 2; mf++)
                #pragma unroll
                for (int nf = 0; nf < 8; nf++) {
                    asm volatile(
                        "mma.sync.aligned.m16n8k16.row.col.f32.bf16.bf16.f32 "
                        "{%0,%1,%2,%3}, {%4,%5,%6,%7}, {%8,%9}, {%0,%1,%2,%3};"
                        : "+f"(c[mf][nf][0]), "+f"(c[mf][nf][1]),
                          "+f"(c[mf][nf][2]), "+f"(c[mf][nf][3])
                        : "r"(af[mf][0]), "r"(af[mf][1]), "r"(af[mf][2]), "r"(af[mf][3]),
                          "r"(bf[nf][0]), "r"(bf[nf][1]));
                }
        }
        __syncthreads();
    }

    // ---- epilogue: add bias + residual, accumulate sum/sumsq ----
    float sums[2][2] = {{0.f, 0.f}, {0.f, 0.f}};
    float sqs [2][2] = {{0.f, 0.f}, {0.f, 0.f}};
    #pragma unroll
    for (int mf = 0; mf < 2; mf++) {
        int row0 = bm + wm + mf * 16 + (lane >> 2);
        int row1 = row0 + 8;
        #pragma unroll
        for (int nf = 0; nf < 8; nf++) {
            int col = wn + nf * 8 + (lane & 3) * 2;
            float bx = __ldg(bias + col), by = __ldg(bias + col + 1);
            float2 r0 = make_float2(0.f, 0.f), r1 = make_float2(0.f, 0.f);
            if (row0 < M) r0 = *reinterpret_cast<const float2*>(res + (size_t)row0 * N + col);
            if (row1 < M) r1 = *reinterpret_cast<const float2*>(res + (size_t)row1 * N + col);
            float v0x = c[mf][nf][0] + bx + r0.x;
            float v0y = c[mf][nf][1] + by + r0.y;
            float v1x = c[mf][nf][2] + bx + r1.x;
            float v1y = c[mf][nf][3] + by + r1.y;
            c[mf][nf][0] = v0x; c[mf][nf][1] = v0y;
            c[mf][nf][2] = v1x; c[mf][nf][3] = v1y;
            sums[mf][0] += v0x + v0y;
            sqs [mf][0] += v0x * v0x + v0y * v0y;
            sums[mf][1] += v1x + v1y;
            sqs [mf][1] += v1x * v1x + v1y * v1y;
        }
    }
    // reduce over the 4 lanes of a quad (same row, different cols)
    #pragma unroll
    for (int o = 1; o <= 2; o <<= 1) {
        #pragma unroll
        for (int mf = 0; mf < 2; mf++)
            #pragma unroll
            for (int hf = 0; hf < 2; hf++) {
                sums[mf][hf] += __shfl_xor_sync(0xffffffffu, sums[mf][hf], o);
                sqs [mf][hf] += __shfl_xor_sync(0xffffffffu, sqs [mf][hf], o);
            }
    }
    if ((lane & 3) == 0) {
        #pragma unroll
        for (int mf = 0; mf < 2; mf++)
            #pragma unroll
            for (int hf = 0; hf < 2; hf++) {
                int rl = wm + mf * 16 + (lane >> 2) + 8 * hf;
                rsum[wid & 3][rl] = sums[mf][hf];
                rsq [wid & 3][rl] = sqs [mf][hf];
            }
    }
    __syncthreads();

    // ---- normalize + store ----
    #pragma unroll
    for (int mf = 0; mf < 2; mf++) {
        int rl0 = wm + mf * 16 + (lane >> 2);
        int rl1 = rl0 + 8;
        float s0 = rsum[0][rl0] + rsum[1][rl0] + rsum[2][rl0] + rsum[3][rl0];
        float q0 = rsq [0][rl0] + rsq [1][rl0] + rsq [2][rl0] + rsq [3][rl0];
        float s1 = rsum[0][rl1] + rsum[1][rl1] + rsum[2][rl1] + rsum[3][rl1];
        float q1 = rsq [0][rl1] + rsq [1][rl1] + rsq [2][rl1] + rsq [3][rl1];
        float m0 = s0 * (1.f / 256.f);
        float m1 = s1 * (1.f / 256.f);
        float rs0 = rsqrtf(fmaxf(q0 * (1.f / 256.f) - m0 * m0, 0.f) + 1e-5f);
        float rs1 = rsqrtf(fmaxf(q1 * (1.f / 256.f) - m1 * m1, 0.f) + 1e-5f);
        int row0 = bm + rl0;
        int row1 = bm + rl1;
        #pragma unroll
        for (int nf = 0; nf < 8; nf++) {
            int col = wn + nf * 8 + (lane & 3) * 2;
            float gx = __ldg(gam + col), gy = __ldg(gam + col + 1);
            float bx = __ldg(bet + col), by = __ldg(bet + col + 1);
            if (row0 < M) {
                float2 o0;
                o0.x = (c[mf][nf][0] - m0) * rs0 * gx + bx;
                o0.y = (c[mf][nf][1] - m0) * rs0 * gy + by;
                *reinterpret_cast<float2*>(out + (size_t)row0 * N + col) = o0;
            }
            if (row1 < M) {
                float2 o1;
                o1.x = (c[mf][nf][2] - m1) * rs1 * gx + bx;
                o1.y = (c[mf][nf][3] - m1) * rs1 * gy + by;
                *reinterpret_cast<float2*>(out + (size_t)row1 * N + col) = o1;
            }
        }
    }
}

// ---------------- deformable sampling ----------
__global__ __launch_bounds__(256)
void sample_kernel(const __nv_bfloat16* __restrict__ valh,
                   const float* __restrict__ refp,
                   const float* __restrict__ ol,     // (LQ, 384): off | logits
                   const int* __restrict__ shapes,
                   const int* __restrict__ starts,
                   float* __restrict__ acc) {
    __shared__ float aw_s[NH * 16];
    __shared__ __align__(16) int2 pw_s[512];

    int lq = blockIdx.x;
    int tid = threadIdx.x;
    int h = tid >> 5;
    int lane = tid & 31;
    const unsigned FULL = 0xffffffffu;

    {
        const float* lg = ol + (size_t)lq * 384 + 256 + h * 16;
        float myl = (lane < 16) ? lg[lane] : -1e30f;
        float mx = myl;
        #pragma unroll
        for (int o = 8; o; o >>= 1) mx = fmaxf(mx, __shfl_xor_sync(FULL, mx, o));
        float e = (lane < 16) ? __expf(myl - mx) : 0.f;
        float sum = e;
        #pragma unroll
        for (int o = 16; o; o >>= 1) sum += __shfl_xor_sync(FULL, sum, o);
        float inv = 1.f / sum;
        if (lane < 16) aw_s[h * 16 + lane] = e * inv;
    }
    __syncthreads();

    if (tid < 128) {
        int jh = tid >> 4;
        int p = tid & 15;
        int l = p >> 2;

        int Hl = __ldg(&shapes[l * 2 + 0]);
        int Wl = __ldg(&shapes[l * 2 + 1]);
        int st = __ldg(&starts[l]);
        float fW = (float)Wl, fH = (float)Hl;

        float rx = __ldg(&refp[(size_t)lq * 8 + l * 2 + 0]);
        float ry = __ldg(&refp[(size_t)lq * 8 + l * 2 + 1]);
        float2 oxy = __ldg(reinterpret_cast<const float2*>(ol + (size_t)lq * 384 + jh * 32 + p * 2));

        float x = rx * fW + oxy.x - 0.5f;
        float y = ry * fH + oxy.y - 0.5f;
        float x0f = floorf(x), y0f = floorf(y);
        float fx = x - x0f, fy = y - y0f;
        int x0 = (int)x0f, y0 = (int)y0f;
        float aw = aw_s[jh * 16 + p];

        float wx1 = fx * aw, wx0 = aw - wx1;
        float w00 = wx0 * (1.f - fy), w01 = wx1 * (1.f - fy);
        float w10 = wx0 * fy,         w11 = wx1 * fy;

        bool vx0 = (unsigned)x0 < (unsigned)Wl;
        bool vx1 = (unsigned)(x0 + 1) < (unsigned)Wl;
        bool vy0 = (unsigned)y0 < (unsigned)Hl;
        bool vy1 = (unsigned)(y0 + 1) < (unsigned)Hl;
        if (!(vx0 && vy0)) w00 = 0.f;
        if (!(vx1 && vy0)) w01 = 0.f;
        if (!(vx0 && vy1)) w10 = 0.f;
        if (!(vx1 && vy1)) w11 = 0.f;

        int xc0 = min(max(x0, 0), Wl - 1);
        int xc1 = min(max(x0 + 1, 0), Wl - 1);
        int yc0 = min(max(y0, 0), Hl - 1);
        int yc1 = min(max(y0 + 1, 0), Hl - 1);
        int base = st * 512 + jh * 64;
        int r0 = yc0 * Wl, r1 = yc1 * Wl;

        int4 e0, e1;
        e0.x = base + (r0 + xc0) * 512; e0.y = __float_as_int(w00);
        e0.z = base + (r0 + xc1) * 512; e0.w = __float_as_int(w01);
        e1.x = base + (r1 + xc0) * 512; e1.y = __float_as_int(w10);
        e1.z = base + (r1 + xc1) * 512; e1.w = __float_as_int(w11);
        int4* dst = reinterpret_cast<int4*>(&pw_s[tid * 4]);
        dst[0] = e0;
        dst[1] = e1;
    }
    __syncthreads();

    {
        const int2* pw = pw_s + h * 64;
        int cor = lane >> 2;
        int ch = lane & 3;
        const char* vbase = reinterpret_cast<const char*>(valh) + 16 * ch;
        int2 q[8];
        #pragma unroll
        for (int i = 0; i < 8; i++) q[i] = pw[i * 8 + cor];
        float a[8];
        #pragma unroll
        for (int i = 0; i < 8; i++) a[i] = 0.f;
        #pragma unroll
        for (int i = 0; i < 8; i++) {
            float w = __int_as_float(q[i].y);
            uint4 v = *reinterpret_cast<const uint4*>(vbase + q[i].x);
            float2 f0 = __bfloat1622float2(*reinterpret_cast<__nv_bfloat162*>(&v.x));
            float2 f1 = __bfloat1622float2(*reinterpret_cast<__nv_bfloat162*>(&v.y));
            float2 f2 = __bfloat1622float2(*reinterpret_cast<__nv_bfloat162*>(&v.z));
            float2 f3 = __bfloat1622float2(*reinterpret_cast<__nv_bfloat162*>(&v.w));
            a[0] += w * f0.x; a[1] += w * f0.y;
            a[2] += w * f1.x; a[3] += w * f1.y;
            a[4] += w * f2.x; a[5] += w * f2.y;
            a[6] += w * f3.x; a[7] += w * f3.y;
        }
        #pragma unroll
        for (int o = 4; o <= 16; o <<= 1)
            #pragma unroll
            for (int i = 0; i < 8; i++)
                a[i] += __shfl_xor_sync(FULL, a[i], o);
        if (lane < 4) {
            float* dst = acc + (size_t)lq * 256 + h * 32 + 8 * ch;
            float4 o0; o0.x = a[0]; o0.y = a[1]; o0.z = a[2]; o0.w = a[3];
            float4 o1; o1.x = a[4]; o1.y = a[5]; o1.z = a[6]; o1.w = a[7];
            *reinterpret_cast<float4*>(dst) = o0;
            *reinterpret_cast<float4*>(dst + 4) = o1;
        }
    }
}

// ---------------- host ----------------
extern "C" void kernel_launch(void* const* d_in, const int* in_sizes, int n_in,
                              void* d_out, int out_size) {
    const float* query = (const float*)d_in[0];
    const float* refp  = (const float*)d_in[1];
    const float* pos   = (const float*)d_in[2];
    const int*   shp   = (const int*)d_in[3];
    const int*   sti   = (const int*)d_in[4];
    const float* w_off = (const float*)d_in[5];
    const float* b_off = (const float*)d_in[6];
    const float* w_attn= (const float*)d_in[7];
    const float* b_attn= (const float*)d_in[8];
    const float* w_val = (const float*)d_in[9];
    const float* b_val = (const float*)d_in[10];
    const float* w_out = (const float*)d_in[11];
    const float* b_out = (const float*)d_in[12];
    const float* g1    = (const float*)d_in[13];
    const float* be1   = (const float*)d_in[14];
    const float* w1    = (const float*)d_in[15];
    const float* b1    = (const float*)d_in[16];
    const float* w2    = (const float*)d_in[17];
    const float* b2    = (const float*)d_in[18];
    const float* g2    = (const float*)d_in[19];
    const float* be2   = (const float*)d_in[20];
    float* out = (float*)d_out;

    float *ol, *acc, *x, *h, *wcat, *bcat;
    __nv_bfloat16* valh;
    cudaGetSymbolAddress((void**)&valh, g_valh);
    cudaGetSymbolAddress((void**)&ol,   g_ol);
    cudaGetSymbolAddress((void**)&acc,  g_acc);
    cudaGetSymbolAddress((void**)&x,    g_x);
    cudaGetSymbolAddress((void**)&h,    g_h);
    cudaGetSymbolAddress((void**)&wcat, g_wcat);
    cudaGetSymbolAddress((void**)&bcat, g_bcat);

    const int M = LQ;
    dim3 grid_n256(2, (M + 127) / 128);
    dim3 grid_n384(3, (M + 127) / 128);
    int grid_ln = (M + 63) / 64;

    cudaStream_t s1;
    cudaStreamCreateWithFlags(&s1, cudaStreamNonBlocking);
    cudaEvent_t e0, e1;
    cudaEventCreateWithFlags(&e0, cudaEventDisableTiming);
    cudaEventCreateWithFlags(&e1, cudaEventDisableTiming);

    cudaEventRecord(e0, 0);
    cudaStreamWaitEvent(s1, e0, 0);
    tgemm<<<grid_n256, 256, 0, s1>>>(query, nullptr, w_val, b_val, valh, M, 256, 2);

    pack_w<<<(256 * 384 + 255) / 256, 256>>>(w_off, b_off, w_attn, b_attn, wcat, bcat);
    tgemm<<<grid_n384, 256>>>(query, pos, wcat, bcat, ol, M, 384, 0);

    cudaEventRecord(e1, s1);
    cudaStreamWaitEvent(0, e1, 0);

    sample_kernel<<<LQ, 256>>>(valh, refp, ol, shp, sti, acc);
    // x = LN(query + acc@w_out + b_out)
    tgemm_ln<<<grid_ln, 256>>>(acc, w_out, b_out, query, g1, be1, x, M);
    // h = relu(x@w1 + b1)
    tgemm<<<grid_n256, 256>>>(x, nullptr, w1, b1, h, M, 256, 1);
    // out = LN(x + h@w2 + b2)
    tgemm_ln<<<grid_ln, 256>>>(h, w2, b2, x, g2, be2, out, M);
}

// round 12
// speedup vs baseline: 1.1965x; 1.0922x over previous
#include <cuda_runtime.h>
#include <cuda_bf16.h>
#include <cstdint>

#define LQ 43054
#define D  256
#define NH 8
#define NL 4
#define NP 4
#define HD 32

// ---------------- scratch (device globals) ----------------
__device__ __nv_bfloat16 g_valh[LQ * D];
__device__ __nv_bfloat16 g_acch[LQ * D];
__device__ __nv_bfloat16 g_hh  [LQ * D];
__device__ float g_ol  [LQ * 384];
__device__ float g_x   [LQ * D];
__device__ __nv_bfloat16 g_wvalh[256 * 256];
__device__ __nv_bfloat16 g_wouth[256 * 256];
__device__ __nv_bfloat16 g_w1h  [256 * 256];
__device__ __nv_bfloat16 g_w2h  [256 * 256];
__device__ __nv_bfloat16 g_wcath[256 * 384];
__device__ float g_bcat[384];

// ---------------- pack all weights to bf16 ----------------
__global__ void pack_all(const float* __restrict__ w_val, const float* __restrict__ w_out,
                         const float* __restrict__ w1, const float* __restrict__ w2,
                         const float* __restrict__ w_off, const float* __restrict__ w_attn,
                         const float* __restrict__ b_off, const float* __restrict__ b_attn,
                         __nv_bfloat16* __restrict__ wvalh, __nv_bfloat16* __restrict__ wouth,
                         __nv_bfloat16* __restrict__ w1h, __nv_bfloat16* __restrict__ w2h,
                         __nv_bfloat16* __restrict__ wcath, float* __restrict__ bcat) {
    int i = blockIdx.x * blockDim.x + threadIdx.x;
    if (i < 65536) { wvalh[i] = __float2bfloat16(w_val[i]); return; }
    i -= 65536;
    if (i < 65536) { wouth[i] = __float2bfloat16(w_out[i]); return; }
    i -= 65536;
    if (i < 65536) { w1h[i] = __float2bfloat16(w1[i]); return; }
    i -= 65536;
    if (i < 65536) { w2h[i] = __float2bfloat16(w2[i]); return; }
    i -= 65536;
    if (i < 98304) {
        int k = i / 384, n = i % 384;
        wcath[i] = __float2bfloat16(n < 256 ? w_off[k * 256 + n] : w_attn[k * 128 + (n - 256)]);
        return;
    }
    i -= 98304;
    if (i < 384) bcat[i] = (i < 256) ? b_off[i] : b_attn[i - 256];
}

// ---------------- bf16 tensor-core GEMM (BM=128 BN=128 BK=64) ----------------
// A fp32 (+A2) or bf16 (abf=1); B bf16.
// mode: 0 fp32 out, 1 fp32+ReLU, 2 bf16 out, 3 bf16+ReLU
__global__ __launch_bounds__(256, 2)
void tgemm(const void* __restrict__ Av, const float* __restrict__ A2,
           const __nv_bfloat16* __restrict__ B,
           const float* __restrict__ bias, void* __restrict__ Cv,
           int M, int N, int mode, int abf) {
    constexpr int K = 256;
    constexpr int LDA = 72;
    constexpr int LDB = 136;
    __shared__ __align__(16) __nv_bfloat16 As[128 * LDA];
    __shared__ __align__(16) __nv_bfloat16 Bs[64 * LDB];

    int tid = threadIdx.x;
    int lane = tid & 31;
    int wid = tid >> 5;
    int bm = blockIdx.y * 128;
    int bn = blockIdx.x * 128;
    int wm = (wid >> 2) * 64;
    int wn = (wid & 3) * 32;

    float c[4][4][4];
    #pragma unroll
    for (int i = 0; i < 4; i++)
        #pragma unroll
        for (int j = 0; j < 4; j++)
            #pragma unroll
            for (int r = 0; r < 4; r++) c[i][j][r] = 0.f;

    int a_row = lane & 15;
    int a_koff = (lane >> 4) * 8;
    int b_krow = (lane & 7) + ((lane >> 3) & 1) * 8;
    int b_noff = (lane >> 4) * 8;

    for (int k0 = 0; k0 < K; k0 += 64) {
        if (abf) {
            const __nv_bfloat16* Ah = (const __nv_bfloat16*)Av;
            #pragma unroll
            for (int i = 0; i < 4; i++) {
                int slot = tid + i * 256;
                int row = slot >> 3;
                int k8 = (slot & 7) * 8;
                uint4 v = make_uint4(0, 0, 0, 0);
                if (bm + row < M)
                    v = *reinterpret_cast<const uint4*>(Ah + (size_t)(bm + row) * K + k0 + k8);
                *reinterpret_cast<uint4*>(&As[row * LDA + k8]) = v;
            }
        } else {
            const float* A = (const float*)Av;
            #pragma unroll
            for (int i = 0; i < 8; i++) {
                int slot = tid + i * 256;
                int row = slot >> 4;
                int k4 = (slot & 15) * 4;
                float4 v = make_float4(0.f, 0.f, 0.f, 0.f);
                if (bm + row < M) {
                    v = *reinterpret_cast<const float4*>(A + (size_t)(bm + row) * K + k0 + k4);
                    if (A2) {
                        float4 u = *reinterpret_cast<const float4*>(A2 + (size_t)(bm + row) * K + k0 + k4);
                        v.x += u.x; v.y += u.y; v.z += u.z; v.w += u.w;
                    }
                }
                __nv_bfloat162 p0 = __floats2bfloat162_rn(v.x, v.y);
                __nv_bfloat162 p1 = __floats2bfloat162_rn(v.z, v.w);
                uint2 st;
                st.x = *reinterpret_cast<uint32_t*>(&p0);
                st.y = *reinterpret_cast<uint32_t*>(&p1);
                *reinterpret_cast<uint2*>(&As[row * LDA + k4]) = st;
            }
        }
        // stage B: 64 k-rows x 128 n (bf16 copy)
        #pragma unroll
        for (int i = 0; i < 4; i++) {
            int slot = tid + i * 256;
            int kk = slot >> 4;
            int n8 = (slot & 15) * 8;
            uint4 v = *reinterpret_cast<const uint4*>(B + (size_t)(k0 + kk) * N + bn + n8);
            *reinterpret_cast<uint4*>(&Bs[kk * LDB + n8]) = v;
        }
        __syncthreads();

        #pragma unroll
        for (int ks = 0; ks < 4; ks++) {
            int kbase = ks * 16;
            uint32_t af[4][4];
            #pragma unroll
            for (int mf = 0; mf < 4; mf++) {
                const __nv_bfloat16* p = &As[(wm + mf * 16 + a_row) * LDA + kbase + a_koff];
                uint32_t addr = (uint32_t)__cvta_generic_to_shared(p);
                asm volatile("ldmatrix.sync.aligned.m8n8.x4.shared.b16 {%0,%1,%2,%3}, [%4];"
                             : "=r"(af[mf][0]), "=r"(af[mf][1]), "=r"(af[mf][2]), "=r"(af[mf][3])
                             : "r"(addr));
            }
            uint32_t bf[4][2];
            #pragma unroll
            for (int n16 = 0; n16 < 2; n16++) {
                const __nv_bfloat16* p = &Bs[(kbase + b_krow) * LDB + wn + n16 * 16 + b_noff];
                uint32_t addr = (uint32_t)__cvta_generic_to_shared(p);
                asm volatile("ldmatrix.sync.aligned.m8n8.x4.trans.shared.b16 {%0,%1,%2,%3}, [%4];"
                             : "=r"(bf[n16 * 2][0]), "=r"(bf[n16 * 2][1]),
                               "=r"(bf[n16 * 2 + 1][0]), "=r"(bf[n16 * 2 + 1][1])
                             : "r"(addr));
            }
            #pragma unroll
            for (int mf = 0; mf < 4; mf++)
                #pragma unroll
                for (int nf = 0; nf < 4; nf++) {
                    asm volatile(
                        "mma.sync.aligned.m16n8k16.row.col.f32.bf16.bf16.f32 "
                        "{%0,%1,%2,%3}, {%4,%5,%6,%7}, {%8,%9}, {%0,%1,%2,%3};"
                        : "+f"(c[mf][nf][0]), "+f"(c[mf][nf][1]),
                          "+f"(c[mf][nf][2]), "+f"(c[mf][nf][3])
                        : "r"(af[mf][0]), "r"(af[mf][1]), "r"(af[mf][2]), "r"(af[mf][3]),
                          "r"(bf[nf][0]), "r"(bf[nf][1]));
                }
        }
        __syncthreads();
    }

    #pragma unroll
    for (int mf = 0; mf < 4; mf++) {
        int row0 = bm + wm + mf * 16 + (lane >> 2);
        #pragma unroll
        for (int nf = 0; nf < 4; nf++) {
            int col = bn + wn + nf * 8 + (lane & 3) * 2;
            float bx = bias[col], by = bias[col + 1];
            float2 v0, v1;
            v0.x = c[mf][nf][0] + bx; v0.y = c[mf][nf][1] + by;
            v1.x = c[mf][nf][2] + bx; v1.y = c[mf][nf][3] + by;
            if (mode & 1) {
                v0.x = fmaxf(v0.x, 0.f); v0.y = fmaxf(v0.y, 0.f);
                v1.x = fmaxf(v1.x, 0.f); v1.y = fmaxf(v1.y, 0.f);
            }
            if (mode >= 2) {
                __nv_bfloat16* C = (__nv_bfloat16*)Cv;
                if (row0 < M)
                    *reinterpret_cast<__nv_bfloat162*>(C + (size_t)row0 * N + col) =
                        __floats2bfloat162_rn(v0.x, v0.y);
                if (row0 + 8 < M)
                    *reinterpret_cast<__nv_bfloat162*>(C + (size_t)(row0 + 8) * N + col) =
                        __floats2bfloat162_rn(v1.x, v1.y);
            } else {
                float* C = (float*)Cv;
                if (row0 < M)
                    *reinterpret_cast<float2*>(C + (size_t)row0 * N + col) = v0;
                if (row0 + 8 < M)
                    *reinterpret_cast<float2*>(C + (size_t)(row0 + 8) * N + col) = v1;
            }
        }
    }
}

// ---------------- bf16 GEMM + residual + LayerNorm fused (A bf16, B bf16) ----
// out[M,256] = LN(res + A@B + bias).  BM=64, BN=256, 8 warps (2x4), warp 32x64.
__global__ __launch_bounds__(256)
void tgemm_ln(const __nv_bfloat16* __restrict__ A, const __nv_bfloat16* __restrict__ B,
              const float* __restrict__ bias, const float* __restrict__ res,
              const float* __restrict__ gam, const float* __restrict__ bet,
              float* __restrict__ out, int M) {
    constexpr int K = 256;
    constexpr int N = 256;
    constexpr int LDA = 72;
    constexpr int LDB = 264;
    __shared__ __align__(16) __nv_bfloat16 As[64 * LDA];
    __shared__ __align__(16) __nv_bfloat16 Bs[64 * LDB];
    __shared__ float rsum[4][64];
    __shared__ float rsq[4][64];

    int tid = threadIdx.x;
    int lane = tid & 31;
    int wid = tid >> 5;
    int bm = blockIdx.x * 64;
    int wm = (wid >> 2) * 32;
    int wn = (wid & 3) * 64;

    float c[2][8][4];
    #pragma unroll
    for (int i = 0; i < 2; i++)
        #pragma unroll
        for (int j = 0; j < 8; j++)
            #pragma unroll
            for (int r = 0; r < 4; r++) c[i][j][r] = 0.f;

    int a_row = lane & 15;
    int a_koff = (lane >> 4) * 8;
    int b_krow = (lane & 7) + ((lane >> 3) & 1) * 8;
    int b_noff = (lane >> 4) * 8;

    for (int k0 = 0; k0 < K; k0 += 64) {
        // stage A: 64 rows x 64 k (bf16 copy)
        #pragma unroll
        for (int i = 0; i < 2; i++) {
            int slot = tid + i * 256;
            int row = slot >> 3;
            int k8 = (slot & 7) * 8;
            uint4 v = make_uint4(0, 0, 0, 0);
            if (bm + row < M)
                v = *reinterpret_cast<const uint4*>(A + (size_t)(bm + row) * K + k0 + k8);
            *reinterpret_cast<uint4*>(&As[row * LDA + k8]) = v;
        }
        // stage B: 64 k-rows x 256 n (bf16 copy)
        #pragma unroll
        for (int i = 0; i < 8; i++) {
            int slot = tid + i * 256;
            int kk = slot >> 5;
            int n8 = (slot & 31) * 8;
            uint4 v = *reinterpret_cast<const uint4*>(B + (size_t)(k0 + kk) * N + n8);
            *reinterpret_cast<uint4*>(&Bs[kk * LDB + n8]) = v;
        }
        __syncthreads();

        #pragma unroll
        for (int ks = 0; ks < 4; ks++) {
            int kbase = ks * 16;
            uint32_t af[2][4];
            #pragma unroll
            for (int mf = 0; mf < 2; mf++) {
                const __nv_bfloat16* p = &As[(wm + mf * 16 + a_row) * LDA + kbase + a_koff];
                uint32_t addr = (uint32_t)__cvta_generic_to_shared(p);
                asm volatile("ldmatrix.sync.aligned.m8n8.x4.shared.b16 {%0,%1,%2,%3}, [%4];"
                             : "=r"(af[mf][0]), "=r"(af[mf][1]), "=r"(af[mf][2]), "=r"(af[mf][3])
                             : "r"(addr));
            }
            uint32_t bf[8][2];
            #pragma unroll
            for (int n16 = 0; n16 < 4; n16++) {
                const __nv_bfloat16* p = &Bs[(kbase + b_krow) * LDB + wn + n16 * 16 + b_noff];
                uint32_t addr = (uint32_t)__cvta_generic_to_shared(p);
                asm volatile("ldmatrix.sync.aligned.m8n8.x4.trans.shared.b16 {%0,%1,%2,%3}, [%4];"
                             : "=r"(bf[n16 * 2][0]), "=r"(bf[n16 * 2][1]),
                               "=r"(bf[n16 * 2 + 1][0]), "=r"(bf[n16 * 2 + 1][1])
                             : "r"(addr));
            }
            #pragma unroll
            for (int mf = 0; mf < 2; mf++)
                #pragma unroll
                for (int nf = 0; nf < 8; nf++) {
                    asm volatile(
                        "mma.sync.aligned.m16n8k16.row.col.f32.bf16.bf16.f32 "
                        "{%0,%1,%2,%3}, {%4,%5,%6,%7}, {%8,%9}, {%0,%1,%2,%3};"
                        : "+f"(c[mf][nf][0]), "+f"(c[mf][nf][1]),
                          "+f"(c[mf][nf][2]), "+f"(c[mf][nf][3])
                        : "r"(af[mf][0]), "r"(af[mf][1]), "r"(af[mf][2]), "r"(af[mf][3]),
                          "r"(bf[nf][0]), "r"(bf[nf][1]));
                }
        }
        __syncthreads();
    }

    float sums[2][2] = {{0.f, 0.f}, {0.f, 0.f}};
    float sqs [2][2] = {{0.f, 0.f}, {0.f, 0.f}};
    #pragma unroll
    for (int mf = 0; mf < 2; mf++) {
        int row0 = bm + wm + mf * 16 + (lane >> 2);
        int row1 = row0 + 8;
        #pragma unroll
        for (int nf = 0; nf < 8; nf++) {
            int col = wn + nf * 8 + (lane & 3) * 2;
            float bx = __ldg(bias + col), by = __ldg(bias + col + 1);
            float2 r0 = make_float2(0.f, 0.f), r1 = make_float2(0.f, 0.f);
            if (row0 < M) r0 = *reinterpret_cast<const float2*>(res + (size_t)row0 * N + col);
            if (row1 < M) r1 = *reinterpret_cast<const float2*>(res + (size_t)row1 * N + col);
            float v0x = c[mf][nf][0] + bx + r0.x;
            float v0y = c[mf][nf][1] + by + r0.y;
            float v1x = c[mf][nf][2] + bx + r1.x;
            float v1y = c[mf][nf][3] + by + r1.y;
            c[mf][nf][0] = v0x; c[mf][nf][1] = v0y;
            c[mf][nf][2] = v1x; c[mf][nf][3] = v1y;
            sums[mf][0] += v0x + v0y;
            sqs [mf][0] += v0x * v0x + v0y * v0y;
            sums[mf][1] += v1x + v1y;
            sqs [mf][1] += v1x * v1x + v1y * v1y;
        }
    }
    #pragma unroll
    for (int o = 1; o <= 2; o <<= 1) {
        #pragma unroll
        for (int mf = 0; mf < 2; mf++)
            #pragma unroll
            for (int hf = 0; hf < 2; hf++) {
                sums[mf][hf] += __shfl_xor_sync(0xffffffffu, sums[mf][hf], o);
                sqs [mf][hf] += __shfl_xor_sync(0xffffffffu, sqs [mf][hf], o);
            }
    }
    if ((lane & 3) == 0) {
        #pragma unroll
        for (int mf = 0; mf < 2; mf++)
            #pragma unroll
            for (int hf = 0; hf < 2; hf++) {
                int rl = wm + mf * 16 + (lane >> 2) + 8 * hf;
                rsum[wid & 3][rl] = sums[mf][hf];
                rsq [wid & 3][rl] = sqs [mf][hf];
            }
    }
    __syncthreads();

    #pragma unroll
    for (int mf = 0; mf < 2; mf++) {
        int rl0 = wm + mf * 16 + (lane >> 2);
        int rl1 = rl0 + 8;
        float s0 = rsum[0][rl0] + rsum[1][rl0] + rsum[2][rl0] + rsum[3][rl0];
        float q0 = rsq [0][rl0] + rsq [1][rl0] + rsq [2][rl0] + rsq [3][rl0];
        float s1 = rsum[0][rl1] + rsum[1][rl1] + rsum[2][rl1] + rsum[3][rl1];
        float q1 = rsq [0][rl1] + rsq [1][rl1] + rsq [2][rl1] + rsq [3][rl1];
        float m0 = s0 * (1.f / 256.f);
        float m1 = s1 * (1.f / 256.f);
        float rs0 = rsqrtf(fmaxf(q0 * (1.f / 256.f) - m0 * m0, 0.f) + 1e-5f);
        float rs1 = rsqrtf(fmaxf(q1 * (1.f / 256.f) - m1 * m1, 0.f) + 1e-5f);
        int row0 = bm + rl0;
        int row1 = bm + rl1;
        #pragma unroll
        for (int nf = 0; nf < 8; nf++) {
            int col = wn + nf * 8 + (lane & 3) * 2;
            float gx = __ldg(gam + col), gy = __ldg(gam + col + 1);
            float bx = __ldg(bet + col), by = __ldg(bet + col + 1);
            if (row0 < M) {
                float2 o0;
                o0.x = (c[mf][nf][0] - m0) * rs0 * gx + bx;
                o0.y = (c[mf][nf][1] - m0) * rs0 * gy + by;
                *reinterpret_cast<float2*>(out + (size_t)row0 * N + col) = o0;
            }
            if (row1 < M) {
                float2 o1;
                o1.x = (c[mf][nf][2] - m1) * rs1 * gx + bx;
                o1.y = (c[mf][nf][3] - m1) * rs1 * gy + by;
                *reinterpret_cast<float2*>(out + (size_t)row1 * N + col) = o1;
            }
        }
    }
}

// ---------------- deformable sampling (bf16 out) ----------
__global__ __launch_bounds__(256)
void sample_kernel(const __nv_bfloat16* __restrict__ valh,
                   const float* __restrict__ refp,
                   const float* __restrict__ ol,
                   const int* __restrict__ shapes,
                   const int* __restrict__ starts,
                   __nv_bfloat16* __restrict__ acc) {
    __shared__ float aw_s[NH * 16];
    __shared__ __align__(16) int2 pw_s[512];

    int lq = blockIdx.x;
    int tid = threadIdx.x;
    int h = tid >> 5;
    int lane = tid & 31;
    const unsigned FULL = 0xffffffffu;

    {
        const float* lg = ol + (size_t)lq * 384 + 256 + h * 16;
        float myl = (lane < 16) ? lg[lane] : -1e30f;
        float mx = myl;
        #pragma unroll
        for (int o = 8; o; o >>= 1) mx = fmaxf(mx, __shfl_xor_sync(FULL, mx, o));
        float e = (lane < 16) ? __expf(myl - mx) : 0.f;
        float sum = e;
        #pragma unroll
        for (int o = 16; o; o >>= 1) sum += __shfl_xor_sync(FULL, sum, o);
        float inv = 1.f / sum;
        if (lane < 16) aw_s[h * 16 + lane] = e * inv;
    }
    __syncthreads();

    if (tid < 128) {
        int jh = tid >> 4;
        int p = tid & 15;
        int l = p >> 2;

        int Hl = __ldg(&shapes[l * 2 + 0]);
        int Wl = __ldg(&shapes[l * 2 + 1]);
        int st = __ldg(&starts[l]);
        float fW = (float)Wl, fH = (float)Hl;

        float rx = __ldg(&refp[(size_t)lq * 8 + l * 2 + 0]);
        float ry = __ldg(&refp[(size_t)lq * 8 + l * 2 + 1]);
        float2 oxy = __ldg(reinterpret_cast<const float2*>(ol + (size_t)lq * 384 + jh * 32 + p * 2));

        float x = rx * fW + oxy.x - 0.5f;
        float y = ry * fH + oxy.y - 0.5f;
        float x0f = floorf(x), y0f = floorf(y);
        float fx = x - x0f, fy = y - y0f;
        int x0 = (int)x0f, y0 = (int)y0f;
        float aw = aw_s[jh * 16 + p];

        float wx1 = fx * aw, wx0 = aw - wx1;
        float w00 = wx0 * (1.f - fy), w01 = wx1 * (1.f - fy);
        float w10 = wx0 * fy,         w11 = wx1 * fy;

        bool vx0 = (unsigned)x0 < (unsigned)Wl;
        bool vx1 = (unsigned)(x0 + 1) < (unsigned)Wl;
        bool vy0 = (unsigned)y0 < (unsigned)Hl;
        bool vy1 = (unsigned)(y0 + 1) < (unsigned)Hl;
        if (!(vx0 && vy0)) w00 = 0.f;
        if (!(vx1 && vy0)) w01 = 0.f;
        if (!(vx0 && vy1)) w10 = 0.f;
        if (!(vx1 && vy1)) w11 = 0.f;

        int xc0 = min(max(x0, 0), Wl - 1);
        int xc1 = min(max(x0 + 1, 0), Wl - 1);
        int yc0 = min(max(y0, 0), Hl - 1);
        int yc1 = min(max(y0 + 1, 0), Hl - 1);
        int base = st * 512 + jh * 64;
        int r0 = yc0 * Wl, r1 = yc1 * Wl;

        int4 e0, e1;
        e0.x = base + (r0 + xc0) * 512; e0.y = __float_as_int(w00);
        e0.z = base + (r0 + xc1) * 512; e0.w = __float_as_int(w01);
        e1.x = base + (r1 + xc0) * 512; e1.y = __float_as_int(w10);
        e1.z = base + (r1 + xc1) * 512; e1.w = __float_as_int(w11);
        int4* dst = reinterpret_cast<int4*>(&pw_s[tid * 4]);
        dst[0] = e0;
        dst[1] = e1;
    }
    __syncthreads();

    {
        const int2* pw = pw_s + h * 64;
        int cor = lane >> 2;
        int ch = lane & 3;
        const char* vbase = reinterpret_cast<const char*>(valh) + 16 * ch;
        int2 q[8];
        #pragma unroll
        for (int i = 0; i < 8; i++) q[i] = pw[i * 8 + cor];
        float a[8];
        #pragma unroll
        for (int i = 0; i < 8; i++) a[i] = 0.f;
        #pragma unroll
        for (int i = 0; i < 8; i++) {
            float w = __int_as_float(q[i].y);
            uint4 v = *reinterpret_cast<const uint4*>(vbase + q[i].x);
            float2 f0 = __bfloat1622float2(*reinterpret_cast<__nv_bfloat162*>(&v.x));
            float2 f1 = __bfloat1622float2(*reinterpret_cast<__nv_bfloat162*>(&v.y));
            float2 f2 = __bfloat1622float2(*reinterpret_cast<__nv_bfloat162*>(&v.z));
            float2 f3 = __bfloat1622float2(*reinterpret_cast<__nv_bfloat162*>(&v.w));
            a[0] += w * f0.x; a[1] += w * f0.y;
            a[2] += w * f1.x; a[3] += w * f1.y;
            a[4] += w * f2.x; a[5] += w * f2.y;
            a[6] += w * f3.x; a[7] += w * f3.y;
        }
        #pragma unroll
        for (int o = 4; o <= 16; o <<= 1)
            #pragma unroll
            for (int i = 0; i < 8; i++)
                a[i] += __shfl_xor_sync(FULL, a[i], o);
        if (lane < 4) {
            __nv_bfloat162 b0 = __floats2bfloat162_rn(a[0], a[1]);
            __nv_bfloat162 b1 = __floats2bfloat162_rn(a[2], a[3]);
            __nv_bfloat162 b2 = __floats2bfloat162_rn(a[4], a[5]);
            __nv_bfloat162 b3 = __floats2bfloat162_rn(a[6], a[7]);
            uint4 pk;
            pk.x = *reinterpret_cast<uint32_t*>(&b0);
            pk.y = *reinterpret_cast<uint32_t*>(&b1);
            pk.z = *reinterpret_cast<uint32_t*>(&b2);
            pk.w = *reinterpret_cast<uint32_t*>(&b3);
            *reinterpret_cast<uint4*>(acc + (size_t)lq * 256 + h * 32 + 8 * ch) = pk;
        }
    }
}

// ---------------- host ----------------
extern "C" void kernel_launch(void* const* d_in, const int* in_sizes, int n_in,
                              void* d_out, int out_size) {
    const float* query = (const float*)d_in[0];
    const float* refp  = (const float*)d_in[1];
    const float* pos   = (const float*)d_in[2];
    const int*   shp   = (const int*)d_in[3];
    const int*   sti   = (const int*)d_in[4];
    const float* w_off = (const float*)d_in[5];
    const float* b_off = (const float*)d_in[6];
    const float* w_attn= (const float*)d_in[7];
    const float* b_attn= (const float*)d_in[8];
    const float* w_val = (const float*)d_in[9];
    const float* b_val = (const float*)d_in[10];
    const float* w_out = (const float*)d_in[11];
    const float* b_out = (const float*)d_in[12];
    const float* g1    = (const float*)d_in[13];
    const float* be1   = (const float*)d_in[14];
    const float* w1    = (const float*)d_in[15];
    const float* b1    = (const float*)d_in[16];
    const float* w2    = (const float*)d_in[17];
    const float* b2    = (const float*)d_in[18];
    const float* g2    = (const float*)d_in[19];
    const float* be2   = (const float*)d_in[20];
    float* out = (float*)d_out;

    float *ol, *x, *bcat;
    __nv_bfloat16 *valh, *acch, *hh, *wvalh, *wouth, *w1h, *w2h, *wcath;
    cudaGetSymbolAddress((void**)&valh,  g_valh);
    cudaGetSymbolAddress((void**)&acch,  g_acch);
    cudaGetSymbolAddress((void**)&hh,    g_hh);
    cudaGetSymbolAddress((void**)&ol,    g_ol);
    cudaGetSymbolAddress((void**)&x,     g_x);
    cudaGetSymbolAddress((void**)&wvalh, g_wvalh);
    cudaGetSymbolAddress((void**)&wouth, g_wouth);
    cudaGetSymbolAddress((void**)&w1h,   g_w1h);
    cudaGetSymbolAddress((void**)&w2h,   g_w2h);
    cudaGetSymbolAddress((void**)&wcath, g_wcath);
    cudaGetSymbolAddress((void**)&bcat,  g_bcat);

    const int M = LQ;
    dim3 grid_n256(2, (M + 127) / 128);
    dim3 grid_n384(3, (M + 127) / 128);
    int grid_ln = (M + 63) / 64;

    cudaStream_t s1;
    cudaStreamCreateWithFlags(&s1, cudaStreamNonBlocking);
    cudaEvent_t e0, e1;
    cudaEventCreateWithFlags(&e0, cudaEventDisableTiming);
    cudaEventCreateWithFlags(&e1, cudaEventDisableTiming);

    pack_all<<<(360832 + 255) / 256, 256>>>(w_val, w_out, w1, w2, w_off, w_attn,
                                            b_off, b_attn,
                                            wvalh, wouth, w1h, w2h, wcath, bcat);

    cudaEventRecord(e0, 0);
    cudaStreamWaitEvent(s1, e0, 0);
    // value projection -> bf16 (side stream)
    tgemm<<<grid_n256, 256, 0, s1>>>(query, nullptr, wvalh, b_val, valh, M, 256, 2, 0);
    // merged offsets+logits
    tgemm<<<grid_n384, 256>>>(query, pos, wcath, bcat, ol, M, 384, 0, 0);

    cudaEventRecord(e1, s1);
    cudaStreamWaitEvent(0, e1, 0);

    sample_kernel<<<LQ, 256>>>(valh, refp, ol, shp, sti, acch);
    // x = LN(query + acc@w_out + b_out)
    tgemm_ln<<<grid_ln, 256>>>(acch, wouth, b_out, query, g1, be1, x, M);
    // h = relu(x@w1 + b1) -> bf16
    tgemm<<<grid_n256, 256>>>(x, nullptr, w1h, b1, hh, M, 256, 3, 0);
    // out = LN(x + h@w2 + b2)
    tgemm_ln<<<grid_ln, 256>>>(hh, w2h, b2, x, g2, be2, out, M);
}

// round 13
// speedup vs baseline: 1.2805x; 1.0702x over previous
#include <cuda_runtime.h>
#include <cuda_bf16.h>
#include <cstdint>

#define LQ 43054
#define D  256
#define NH 8
#define NL 4
#define NP 4
#define HD 32

// ---------------- scratch (device globals) ----------------
__device__ __nv_bfloat16 g_valh[LQ * D];
__device__ __nv_bfloat16 g_acch[LQ * D];
__device__ float g_ol  [LQ * 384];
__device__ float g_x   [LQ * D];
__device__ __nv_bfloat16 g_wvalh[256 * 256];
__device__ __nv_bfloat16 g_wouth[256 * 256];
__device__ __nv_bfloat16 g_w1h  [256 * 256];
__device__ __nv_bfloat16 g_w2h  [256 * 256];
__device__ __nv_bfloat16 g_wcath[256 * 384];
__device__ float g_bcat[384];

// ---------------- pack all weights to bf16 ----------------
__global__ void pack_all(const float* __restrict__ w_val, const float* __restrict__ w_out,
                         const float* __restrict__ w1, const float* __restrict__ w2,
                         const float* __restrict__ w_off, const float* __restrict__ w_attn,
                         const float* __restrict__ b_off, const float* __restrict__ b_attn,
                         __nv_bfloat16* __restrict__ wvalh, __nv_bfloat16* __restrict__ wouth,
                         __nv_bfloat16* __restrict__ w1h, __nv_bfloat16* __restrict__ w2h,
                         __nv_bfloat16* __restrict__ wcath, float* __restrict__ bcat) {
    int i = blockIdx.x * blockDim.x + threadIdx.x;
    if (i < 65536) { wvalh[i] = __float2bfloat16(w_val[i]); return; }
    i -= 65536;
    if (i < 65536) { wouth[i] = __float2bfloat16(w_out[i]); return; }
    i -= 65536;
    if (i < 65536) { w1h[i] = __float2bfloat16(w1[i]); return; }
    i -= 65536;
    if (i < 65536) { w2h[i] = __float2bfloat16(w2[i]); return; }
    i -= 65536;
    if (i < 98304) {
        int k = i / 384, n = i % 384;
        wcath[i] = __float2bfloat16(n < 256 ? w_off[k * 256 + n] : w_attn[k * 128 + (n - 256)]);
        return;
    }
    i -= 98304;
    if (i < 384) bcat[i] = (i < 256) ? b_off[i] : b_attn[i - 256];
}

// ---------------- bf16 tensor-core GEMM (BM=128 BN=128 BK=64) ----------------
// mode: 0 fp32 out, 2 bf16 out
__global__ __launch_bounds__(256, 2)
void tgemm(const float* __restrict__ A, const float* __restrict__ A2,
           const __nv_bfloat16* __restrict__ B,
           const float* __restrict__ bias, void* __restrict__ Cv,
           int M, int N, int mode) {
    constexpr int K = 256;
    constexpr int LDA = 72;
    constexpr int LDB = 136;
    __shared__ __align__(16) __nv_bfloat16 As[128 * LDA];
    __shared__ __align__(16) __nv_bfloat16 Bs[64 * LDB];

    int tid = threadIdx.x;
    int lane = tid & 31;
    int wid = tid >> 5;
    int bm = blockIdx.y * 128;
    int bn = blockIdx.x * 128;
    int wm = (wid >> 2) * 64;
    int wn = (wid & 3) * 32;

    float c[4][4][4];
    #pragma unroll
    for (int i = 0; i < 4; i++)
        #pragma unroll
        for (int j = 0; j < 4; j++)
            #pragma unroll
            for (int r = 0; r < 4; r++) c[i][j][r] = 0.f;

    int a_row = lane & 15;
    int a_koff = (lane >> 4) * 8;
    int b_krow = (lane & 7) + ((lane >> 3) & 1) * 8;
    int b_noff = (lane >> 4) * 8;

    for (int k0 = 0; k0 < K; k0 += 64) {
        #pragma unroll
        for (int i = 0; i < 8; i++) {
            int slot = tid + i * 256;
            int row = slot >> 4;
            int k4 = (slot & 15) * 4;
            float4 v = make_float4(0.f, 0.f, 0.f, 0.f);
            if (bm + row < M) {
                v = *reinterpret_cast<const float4*>(A + (size_t)(bm + row) * K + k0 + k4);
                if (A2) {
                    float4 u = *reinterpret_cast<const float4*>(A2 + (size_t)(bm + row) * K + k0 + k4);
                    v.x += u.x; v.y += u.y; v.z += u.z; v.w += u.w;
                }
            }
            __nv_bfloat162 p0 = __floats2bfloat162_rn(v.x, v.y);
            __nv_bfloat162 p1 = __floats2bfloat162_rn(v.z, v.w);
            uint2 st;
            st.x = *reinterpret_cast<uint32_t*>(&p0);
            st.y = *reinterpret_cast<uint32_t*>(&p1);
            *reinterpret_cast<uint2*>(&As[row * LDA + k4]) = st;
        }
        #pragma unroll
        for (int i = 0; i < 4; i++) {
            int slot = tid + i * 256;
            int kk = slot >> 4;
            int n8 = (slot & 15) * 8;
            uint4 v = *reinterpret_cast<const uint4*>(B + (size_t)(k0 + kk) * N + bn + n8);
            *reinterpret_cast<uint4*>(&Bs[kk * LDB + n8]) = v;
        }
        __syncthreads();

        #pragma unroll
        for (int ks = 0; ks < 4; ks++) {
            int kbase = ks * 16;
            uint32_t af[4][4];
            #pragma unroll
            for (int mf = 0; mf < 4; mf++) {
                const __nv_bfloat16* p = &As[(wm + mf * 16 + a_row) * LDA + kbase + a_koff];
                uint32_t addr = (uint32_t)__cvta_generic_to_shared(p);
                asm volatile("ldmatrix.sync.aligned.m8n8.x4.shared.b16 {%0,%1,%2,%3}, [%4];"
                             : "=r"(af[mf][0]), "=r"(af[mf][1]), "=r"(af[mf][2]), "=r"(af[mf][3])
                             : "r"(addr));
            }
            uint32_t bf[4][2];
            #pragma unroll
            for (int n16 = 0; n16 < 2; n16++) {
                const __nv_bfloat16* p = &Bs[(kbase + b_krow) * LDB + wn + n16 * 16 + b_noff];
                uint32_t addr = (uint32_t)__cvta_generic_to_shared(p);
                asm volatile("ldmatrix.sync.aligned.m8n8.x4.trans.shared.b16 {%0,%1,%2,%3}, [%4];"
                             : "=r"(bf[n16 * 2][0]), "=r"(bf[n16 * 2][1]),
                               "=r"(bf[n16 * 2 + 1][0]), "=r"(bf[n16 * 2 + 1][1])
                             : "r"(addr));
            }
            #pragma unroll
            for (int mf = 0; mf < 4; mf++)
                #pragma unroll
                for (int nf = 0; nf < 4; nf++) {
                    asm volatile(
                        "mma.sync.aligned.m16n8k16.row.col.f32.bf16.bf16.f32 "
                        "{%0,%1,%2,%3}, {%4,%5,%6,%7}, {%8,%9}, {%0,%1,%2,%3};"
                        : "+f"(c[mf][nf][0]), "+f"(c[mf][nf][1]),
                          "+f"(c[mf][nf][2]), "+f"(c[mf][nf][3])
                        : "r"(af[mf][0]), "r"(af[mf][1]), "r"(af[mf][2]), "r"(af[mf][3]),
                          "r"(bf[nf][0]), "r"(bf[nf][1]));
                }
        }
        __syncthreads();
    }

    #pragma unroll
    for (int mf = 0; mf < 4; mf++) {
        int row0 = bm + wm + mf * 16 + (lane >> 2);
        #pragma unroll
        for (int nf = 0; nf < 4; nf++) {
            int col = bn + wn + nf * 8 + (lane & 3) * 2;
            float bx = bias[col], by = bias[col + 1];
            float2 v0, v1;
            v0.x = c[mf][nf][0] + bx; v0.y = c[mf][nf][1] + by;
            v1.x = c[mf][nf][2] + bx; v1.y = c[mf][nf][3] + by;
            if (mode == 2) {
                __nv_bfloat16* C = (__nv_bfloat16*)Cv;
                if (row0 < M)
                    *reinterpret_cast<__nv_bfloat162*>(C + (size_t)row0 * N + col) =
                        __floats2bfloat162_rn(v0.x, v0.y);
                if (row0 + 8 < M)
                    *reinterpret_cast<__nv_bfloat162*>(C + (size_t)(row0 + 8) * N + col) =
                        __floats2bfloat162_rn(v1.x, v1.y);
            } else {
                float* C = (float*)Cv;
                if (row0 < M)
                    *reinterpret_cast<float2*>(C + (size_t)row0 * N + col) = v0;
                if (row0 + 8 < M)
                    *reinterpret_cast<float2*>(C + (size_t)(row0 + 8) * N + col) = v1;
            }
        }
    }
}

// ---------------- bf16 GEMM + residual + LayerNorm fused (A bf16, B bf16) ----
// out[M,256] = LN(res + A@B + bias).  BM=64, BN=256, 8 warps (2x4), warp 32x64.
__global__ __launch_bounds__(256)
void tgemm_ln(const __nv_bfloat16* __restrict__ A, const __nv_bfloat16* __restrict__ B,
              const float* __restrict__ bias, const float* __restrict__ res,
              const float* __restrict__ gam, const float* __restrict__ bet,
              float* __restrict__ out, int M) {
    constexpr int K = 256;
    constexpr int N = 256;
    constexpr int LDA = 72;
    constexpr int LDB = 264;
    __shared__ __align__(16) __nv_bfloat16 As[64 * LDA];
    __shared__ __align__(16) __nv_bfloat16 Bs[64 * LDB];
    __shared__ float rsum[4][64];
    __shared__ float rsq[4][64];

    int tid = threadIdx.x;
    int lane = tid & 31;
    int wid = tid >> 5;
    int bm = blockIdx.x * 64;
    int wm = (wid >> 2) * 32;
    int wn = (wid & 3) * 64;

    float c[2][8][4];
    #pragma unroll
    for (int i = 0; i < 2; i++)
        #pragma unroll
        for (int j = 0; j < 8; j++)
            #pragma unroll
            for (int r = 0; r < 4; r++) c[i][j][r] = 0.f;

    int a_row = lane & 15;
    int a_koff = (lane >> 4) * 8;
    int b_krow = (lane & 7) + ((lane >> 3) & 1) * 8;
    int b_noff = (lane >> 4) * 8;

    for (int k0 = 0; k0 < K; k0 += 64) {
        #pragma unroll
        for (int i = 0; i < 2; i++) {
            int slot = tid + i * 256;
            int row = slot >> 3;
            int k8 = (slot & 7) * 8;
            uint4 v = make_uint4(0, 0, 0, 0);
            if (bm + row < M)
                v = *reinterpret_cast<const uint4*>(A + (size_t)(bm + row) * K + k0 + k8);
            *reinterpret_cast<uint4*>(&As[row * LDA + k8]) = v;
        }
        #pragma unroll
        for (int i = 0; i < 8; i++) {
            int slot = tid + i * 256;
            int kk = slot >> 5;
            int n8 = (slot & 31) * 8;
            uint4 v = *reinterpret_cast<const uint4*>(B + (size_t)(k0 + kk) * N + n8);
            *reinterpret_cast<uint4*>(&Bs[kk * LDB + n8]) = v;
        }
        __syncthreads();

        #pragma unroll
        for (int ks = 0; ks < 4; ks++) {
            int kbase = ks * 16;
            uint32_t af[2][4];
            #pragma unroll
            for (int mf = 0; mf < 2; mf++) {
                const __nv_bfloat16* p = &As[(wm + mf * 16 + a_row) * LDA + kbase + a_koff];
                uint32_t addr = (uint32_t)__cvta_generic_to_shared(p);
                asm volatile("ldmatrix.sync.aligned.m8n8.x4.shared.b16 {%0,%1,%2,%3}, [%4];"
                             : "=r"(af[mf][0]), "=r"(af[mf][1]), "=r"(af[mf][2]), "=r"(af[mf][3])
                             : "r"(addr));
            }
            uint32_t bf[8][2];
            #pragma unroll
            for (int n16 = 0; n16 < 4; n16++) {
                const __nv_bfloat16* p = &Bs[(kbase + b_krow) * LDB + wn + n16 * 16 + b_noff];
                uint32_t addr = (uint32_t)__cvta_generic_to_shared(p);
                asm volatile("ldmatrix.sync.aligned.m8n8.x4.trans.shared.b16 {%0,%1,%2,%3}, [%4];"
                             : "=r"(bf[n16 * 2][0]), "=r"(bf[n16 * 2][1]),
                               "=r"(bf[n16 * 2 + 1][0]), "=r"(bf[n16 * 2 + 1][1])
                             : "r"(addr));
            }
            #pragma unroll
            for (int mf = 0; mf < 2; mf++)
                #pragma unroll
                for (int nf = 0; nf < 8; nf++) {
                    asm volatile(
                        "mma.sync.aligned.m16n8k16.row.col.f32.bf16.bf16.f32 "
                        "{%0,%1,%2,%3}, {%4,%5,%6,%7}, {%8,%9}, {%0,%1,%2,%3};"
                        : "+f"(c[mf][nf][0]), "+f"(c[mf][nf][1]),
                          "+f"(c[mf][nf][2]), "+f"(c[mf][nf][3])
                        : "r"(af[mf][0]), "r"(af[mf][1]), "r"(af[mf][2]), "r"(af[mf][3]),
                          "r"(bf[nf][0]), "r"(bf[nf][1]));
                }
        }
        __syncthreads();
    }

    float sums[2][2] = {{0.f, 0.f}, {0.f, 0.f}};
    float sqs [2][2] = {{0.f, 0.f}, {0.f, 0.f}};
    #pragma unroll
    for (int mf = 0; mf < 2; mf++) {
        int row0 = bm + wm + mf * 16 + (lane >> 2);
        int row1 = row0 + 8;
        #pragma unroll
        for (int nf = 0; nf < 8; nf++) {
            int col = wn + nf * 8 + (lane & 3) * 2;
            float bx = __ldg(bias + col), by = __ldg(bias + col + 1);
            float2 r0 = make_float2(0.f, 0.f), r1 = make_float2(0.f, 0.f);
            if (row0 < M) r0 = *reinterpret_cast<const float2*>(res + (size_t)row0 * N + col);
            if (row1 < M) r1 = *reinterpret_cast<const float2*>(res + (size_t)row1 * N + col);
            float v0x = c[mf][nf][0] + bx + r0.x;
            float v0y = c[mf][nf][1] + by + r0.y;
            float v1x = c[mf][nf][2] + bx + r1.x;
            float v1y = c[mf][nf][3] + by + r1.y;
            c[mf][nf][0] = v0x; c[mf][nf][1] = v0y;
            c[mf][nf][2] = v1x; c[mf][nf][3] = v1y;
            sums[mf][0] += v0x + v0y;
            sqs [mf][0] += v0x * v0x + v0y * v0y;
            sums[mf][1] += v1x + v1y;
            sqs [mf][1] += v1x * v1x + v1y * v1y;
        }
    }
    #pragma unroll
    for (int o = 1; o <= 2; o <<= 1) {
        #pragma unroll
        for (int mf = 0; mf < 2; mf++)
            #pragma unroll
            for (int hf = 0; hf < 2; hf++) {
                sums[mf][hf] += __shfl_xor_sync(0xffffffffu, sums[mf][hf], o);
                sqs [mf][hf] += __shfl_xor_sync(0xffffffffu, sqs [mf][hf], o);
            }
    }
    if ((lane & 3) == 0) {
        #pragma unroll
        for (int mf = 0; mf < 2; mf++)
            #pragma unroll
            for (int hf = 0; hf < 2; hf++) {
                int rl = wm + mf * 16 + (lane >> 2) + 8 * hf;
                rsum[wid & 3][rl] = sums[mf][hf];
                rsq [wid & 3][rl] = sqs [mf][hf];
            }
    }
    __syncthreads();

    #pragma unroll
    for (int mf = 0; mf < 2; mf++) {
        int rl0 = wm + mf * 16 + (lane >> 2);
        int rl1 = rl0 + 8;
        float s0 = rsum[0][rl0] + rsum[1][rl0] + rsum[2][rl0] + rsum[3][rl0];
        float q0 = rsq [0][rl0] + rsq [1][rl0] + rsq [2][rl0] + rsq [3][rl0];
        float s1 = rsum[0][rl1] + rsum[1][rl1] + rsum[2][rl1] + rsum[3][rl1];
        float q1 = rsq [0][rl1] + rsq [1][rl1] + rsq [2][rl1] + rsq [3][rl1];
        float m0 = s0 * (1.f / 256.f);
        float m1 = s1 * (1.f / 256.f);
        float rs0 = rsqrtf(fmaxf(q0 * (1.f / 256.f) - m0 * m0, 0.f) + 1e-5f);
        float rs1 = rsqrtf(fmaxf(q1 * (1.f / 256.f) - m1 * m1, 0.f) + 1e-5f);
        int row0 = bm + rl0;
        int row1 = bm + rl1;
        #pragma unroll
        for (int nf = 0; nf < 8; nf++) {
            int col = wn + nf * 8 + (lane & 3) * 2;
            float gx = __ldg(gam + col), gy = __ldg(gam + col + 1);
            float bx = __ldg(bet + col), by = __ldg(bet + col + 1);
            if (row0 < M) {
                float2 o0;
                o0.x = (c[mf][nf][0] - m0) * rs0 * gx + bx;
                o0.y = (c[mf][nf][1] - m0) * rs0 * gy + by;
                *reinterpret_cast<float2*>(out + (size_t)row0 * N + col) = o0;
            }
            if (row1 < M) {
                float2 o1;
                o1.x = (c[mf][nf][2] - m1) * rs1 * gx + bx;
                o1.y = (c[mf][nf][3] - m1) * rs1 * gy + by;
                *reinterpret_cast<float2*>(out + (size_t)row1 * N + col) = o1;
            }
        }
    }
}

// ---------------- fused FFN: out = LN(x + relu(x@W1+b1)@W2+b2) ----------------
// BM=64, BN=256. H kept in smem (bf16). x fp32 in, out fp32.
__global__ __launch_bounds__(256)
void tgemm_ffn(const float* __restrict__ X,
               const __nv_bfloat16* __restrict__ W1, const float* __restrict__ b1,
               const __nv_bfloat16* __restrict__ W2, const float* __restrict__ b2,
               const float* __restrict__ gam, const float* __restrict__ bet,
               float* __restrict__ out, int M) {
    constexpr int K = 256;
    constexpr int N = 256;
    constexpr int LDA = 72;
    constexpr int LDB = 264;
    constexpr int LDH = 264;
    __shared__ __align__(16) __nv_bfloat16 As[64 * LDA];
    __shared__ __align__(16) __nv_bfloat16 Bs[64 * LDB];
    __shared__ __align__(16) __nv_bfloat16 Hs[64 * LDH];
    __shared__ float rsum[4][64];
    __shared__ float rsq[4][64];

    int tid = threadIdx.x;
    int lane = tid & 31;
    int wid = tid >> 5;
    int bm = blockIdx.x * 64;
    int wm = (wid >> 2) * 32;
    int wn = (wid & 3) * 64;

    int a_row = lane & 15;
    int a_koff = (lane >> 4) * 8;
    int b_krow = (lane & 7) + ((lane >> 3) & 1) * 8;
    int b_noff = (lane >> 4) * 8;

    float c[2][8][4];

    // ======== phase A: H = relu(X@W1 + b1) ========
    #pragma unroll
    for (int i = 0; i < 2; i++)
        #pragma unroll
        for (int j = 0; j < 8; j++)
            #pragma unroll
            for (int r = 0; r < 4; r++) c[i][j][r] = 0.f;

    for (int k0 = 0; k0 < K; k0 += 64) {
        // stage X chunk (fp32 -> bf16)
        #pragma unroll
        for (int i = 0; i < 4; i++) {
            int slot = tid + i * 256;
            int row = slot >> 4;
            int k4 = (slot & 15) * 4;
            float4 v = make_float4(0.f, 0.f, 0.f, 0.f);
            if (bm + row < M)
                v = *reinterpret_cast<const float4*>(X + (size_t)(bm + row) * K + k0 + k4);
            __nv_bfloat162 p0 = __floats2bfloat162_rn(v.x, v.y);
            __nv_bfloat162 p1 = __floats2bfloat162_rn(v.z, v.w);
            uint2 st;
            st.x = *reinterpret_cast<uint32_t*>(&p0);
            st.y = *reinterpret_cast<uint32_t*>(&p1);
            *reinterpret_cast<uint2*>(&As[row * LDA + k4]) = st;
        }
        #pragma unroll
        for (int i = 0; i < 8; i++) {
            int slot = tid + i * 256;
            int kk = slot >> 5;
            int n8 = (slot & 31) * 8;
            uint4 v = *reinterpret_cast<const uint4*>(W1 + (size_t)(k0 + kk) * N + n8);
            *reinterpret_cast<uint4*>(&Bs[kk * LDB + n8]) = v;
        }
        __syncthreads();

        #pragma unroll
        for (int ks = 0; ks < 4; ks++) {
            int kbase = ks * 16;
            uint32_t af[2][4];
            #pragma unroll
            for (int mf = 0; mf < 2; mf++) {
                const __nv_bfloat16* p = &As[(wm + mf * 16 + a_row) * LDA + kbase + a_koff];
                uint32_t addr = (uint32_t)__cvta_generic_to_shared(p);
                asm volatile("ldmatrix.sync.aligned.m8n8.x4.shared.b16 {%0,%1,%2,%3}, [%4];"
                             : "=r"(af[mf][0]), "=r"(af[mf][1]), "=r"(af[mf][2]), "=r"(af[mf][3])
                             : "r"(addr));
            }
            uint32_t bf[8][2];
            #pragma unroll
            for (int n16 = 0; n16 < 4; n16++) {
                const __nv_bfloat16* p = &Bs[(kbase + b_krow) * LDB + wn + n16 * 16 + b_noff];
                uint32_t addr = (uint32_t)__cvta_generic_to_shared(p);
                asm volatile("ldmatrix.sync.aligned.m8n8.x4.trans.shared.b16 {%0,%1,%2,%3}, [%4];"
                             : "=r"(bf[n16 * 2][0]), "=r"(bf[n16 * 2][1]),
                               "=r"(bf[n16 * 2 + 1][0]), "=r"(bf[n16 * 2 + 1][1])
                             : "r"(addr));
            }
            #pragma unroll
            for (int mf = 0; mf < 2; mf++)
                #pragma unroll
                for (int nf = 0; nf < 8; nf++) {
                    asm volatile(
                        "mma.sync.aligned.m16n8k16.row.col.f32.bf16.bf16.f32 "
                        "{%0,%1,%2,%3}, {%4,%5,%6,%7}, {%8,%9}, {%0,%1,%2,%3};"
                        : "+f"(c[mf][nf][0]), "+f"(c[mf][nf][1]),
                          "+f"(c[mf][nf][2]), "+f"(c[mf][nf][3])
                        : "r"(af[mf][0]), "r"(af[mf][1]), "r"(af[mf][2]), "r"(af[mf][3]),
                          "r"(bf[nf][0]), "r"(bf[nf][1]));
                }
        }
        __syncthreads();
    }

    // H epilogue: bias + relu -> bf16 smem
    #pragma unroll
    for (int mf = 0; mf < 2; mf++) {
        int rl0 = wm + mf * 16 + (lane >> 2);
        int rl1 = rl0 + 8;
        #pragma unroll
        for (int nf = 0; nf < 8; nf++) {
            int col = wn + nf * 8 + (lane & 3) * 2;
            float bx = __ldg(b1 + col), by = __ldg(b1 + col + 1);
            float h0x = fmaxf(c[mf][nf][0] + bx, 0.f);
            float h0y = fmaxf(c[mf][nf][1] + by, 0.f);
            float h1x = fmaxf(c[mf][nf][2] + bx, 0.f);
            float h1y = fmaxf(c[mf][nf][3] + by, 0.f);
            __nv_bfloat162 p0 = __floats2bfloat162_rn(h0x, h0y);
            __nv_bfloat162 p1 = __floats2bfloat162_rn(h1x, h1y);
            *reinterpret_cast<__nv_bfloat162*>(&Hs[rl0 * LDH + col]) = p0;
            *reinterpret_cast<__nv_bfloat162*>(&Hs[rl1 * LDH + col]) = p1;
        }
    }
    __syncthreads();

    // ======== phase B: out = LN(x + H@W2 + b2) ========
    #pragma unroll
    for (int i = 0; i < 2; i++)
        #pragma unroll
        for (int j = 0; j < 8; j++)
            #pragma unroll
            for (int r = 0; r < 4; r++) c[i][j][r] = 0.f;

    for (int k0 = 0; k0 < K; k0 += 64) {
        #pragma unroll
        for (int i = 0; i < 8; i++) {
            int slot = tid + i * 256;
            int kk = slot >> 5;
            int n8 = (slot & 31) * 8;
            uint4 v = *reinterpret_cast<const uint4*>(W2 + (size_t)(k0 + kk) * N + n8);
            *reinterpret_cast<uint4*>(&Bs[kk * LDB + n8]) = v;
        }
        __syncthreads();

        #pragma unroll
        for (int ks = 0; ks < 4; ks++) {
            int kbase = k0 + ks * 16;
            uint32_t af[2][4];
            #pragma unroll
            for (int mf = 0; mf < 2; mf++) {
                const __nv_bfloat16* p = &Hs[(wm + mf * 16 + a_row) * LDH + kbase + a_koff];
                uint32_t addr = (uint32_t)__cvta_generic_to_shared(p);
                asm volatile("ldmatrix.sync.aligned.m8n8.x4.shared.b16 {%0,%1,%2,%3}, [%4];"
                             : "=r"(af[mf][0]), "=r"(af[mf][1]), "=r"(af[mf][2]), "=r"(af[mf][3])
                             : "r"(addr));
            }
            uint32_t bf[8][2];
            #pragma unroll
            for (int n16 = 0; n16 < 4; n16++) {
                const __nv_bfloat16* p = &Bs[((ks * 16) + b_krow) * LDB + wn + n16 * 16 + b_noff];
                uint32_t addr = (uint32_t)__cvta_generic_to_shared(p);
                asm volatile("ldmatrix.sync.aligned.m8n8.x4.trans.shared.b16 {%0,%1,%2,%3}, [%4];"
                             : "=r"(bf[n16 * 2][0]), "=r"(bf[n16 * 2][1]),
                               "=r"(bf[n16 * 2 + 1][0]), "=r"(bf[n16 * 2 + 1][1])
                             : "r"(addr));
            }
            #pragma unroll
            for (int mf = 0; mf < 2; mf++)
                #pragma unroll
                for (int nf = 0; nf < 8; nf++) {
                    asm volatile(
                        "mma.sync.aligned.m16n8k16.row.col.f32.bf16.bf16.f32 "
                        "{%0,%1,%2,%3}, {%4,%5,%6,%7}, {%8,%9}, {%0,%1,%2,%3};"
                        : "+f"(c[mf][nf][0]), "+f"(c[mf][nf][1]),
                          "+f"(c[mf][nf][2]), "+f"(c[mf][nf][3])
                        : "r"(af[mf][0]), "r"(af[mf][1]), "r"(af[mf][2]), "r"(af[mf][3]),
                          "r"(bf[nf][0]), "r"(bf[nf][1]));
                }
        }
        __syncthreads();
    }

    // LN epilogue (res = X)
    float sums[2][2] = {{0.f, 0.f}, {0.f, 0.f}};
    float sqs [2][2] = {{0.f, 0.f}, {0.f, 0.f}};
    #pragma unroll
    for (int mf = 0; mf < 2; mf++) {
        int row0 = bm + wm + mf * 16 + (lane >> 2);
        int row1 = row0 + 8;
        #pragma unroll
        for (int nf = 0; nf < 8; nf++) {
            int col = wn + nf * 8 + (lane & 3) * 2;
            float bx = __ldg(b2 + col), by = __ldg(b2 + col + 1);
            float2 r0 = make_float2(0.f, 0.f), r1 = make_float2(0.f, 0.f);
            if (row0 < M) r0 = *reinterpret_cast<const float2*>(X + (size_t)row0 * N + col);
            if (row1 < M) r1 = *reinterpret_cast<const float2*>(X + (size_t)row1 * N + col);
            float v0x = c[mf][nf][0] + bx + r0.x;
            float v0y = c[mf][nf][1] + by + r0.y;
            float v1x = c[mf][nf][2] + bx + r1.x;
            float v1y = c[mf][nf][3] + by + r1.y;
            c[mf][nf][0] = v0x; c[mf][nf][1] = v0y;
            c[mf][nf][2] = v1x; c[mf][nf][3] = v1y;
            sums[mf][0] += v0x + v0y;
            sqs [mf][0] += v0x * v0x + v0y * v0y;
            sums[mf][1] += v1x + v1y;
            sqs [mf][1] += v1x * v1x + v1y * v1y;
        }
    }
    #pragma unroll
    for (int o = 1; o <= 2; o <<= 1) {
        #pragma unroll
        for (int mf = 0; mf < 2; mf++)
            #pragma unroll
            for (int hf = 0; hf < 2; hf++) {
                sums[mf][hf] += __shfl_xor_sync(0xffffffffu, sums[mf][hf], o);
                sqs [mf][hf] += __shfl_xor_sync(0xffffffffu, sqs [mf][hf], o);
            }
    }
    if ((lane & 3) == 0) {
        #pragma unroll
        for (int mf = 0; mf < 2; mf++)
            #pragma unroll
            for (int hf = 0; hf < 2; hf++) {
                int rl = wm + mf * 16 + (lane >> 2) + 8 * hf;
                rsum[wid & 3][rl] = sums[mf][hf];
                rsq [wid & 3][rl] = sqs [mf][hf];
            }
    }
    __syncthreads();

    #pragma unroll
    for (int mf = 0; mf < 2; mf++) {
        int rl0 = wm + mf * 16 + (lane >> 2);
        int rl1 = rl0 + 8;
        float s0 = rsum[0][rl0] + rsum[1][rl0] + rsum[2][rl0] + rsum[3][rl0];
        float q0 = rsq [0][rl0] + rsq [1][rl0] + rsq [2][rl0] + rsq [3][rl0];
        float s1 = rsum[0][rl1] + rsum[1][rl1] + rsum[2][rl1] + rsum[3][rl1];
        float q1 = rsq [0][rl1] + rsq [1][rl1] + rsq [2][rl1] + rsq [3][rl1];
        float m0 = s0 * (1.f / 256.f);
        float m1 = s1 * (1.f / 256.f);
        float rs0 = rsqrtf(fmaxf(q0 * (1.f / 256.f) - m0 * m0, 0.f) + 1e-5f);
        float rs1 = rsqrtf(fmaxf(q1 * (1.f / 256.f) - m1 * m1, 0.f) + 1e-5f);
        int row0 = bm + rl0;
        int row1 = bm + rl1;
        #pragma unroll
        for (int nf = 0; nf < 8; nf++) {
            int col = wn + nf * 8 + (lane & 3) * 2;
            float gx = __ldg(gam + col), gy = __ldg(gam + col + 1);
            float bx = __ldg(bet + col), by = __ldg(bet + col + 1);
            if (row0 < M) {
                float2 o0;
                o0.x = (c[mf][nf][0] - m0) * rs0 * gx + bx;
                o0.y = (c[mf][nf][1] - m0) * rs0 * gy + by;
                *reinterpret_cast<float2*>(out + (size_t)row0 * N + col) = o0;
            }
            if (row1 < M) {
                float2 o1;
                o1.x = (c[mf][nf][2] - m1) * rs1 * gx + bx;
                o1.y = (c[mf][nf][3] - m1) * rs1 * gy + by;
                *reinterpret_cast<float2*>(out + (size_t)row1 * N + col) = o1;
            }
        }
    }
}

// ---------------- deformable sampling (softmax fused into phase 1) ----------
__global__ __launch_bounds__(256)
void sample_kernel(const __nv_bfloat16* __restrict__ valh,
                   const float* __restrict__ refp,
                   const float* __restrict__ ol,
                   const int* __restrict__ shapes,
                   const int* __restrict__ starts,
                   __nv_bfloat16* __restrict__ acc) {
    __shared__ __align__(16) int2 pw_s[512];

    int lq = blockIdx.x;
    int tid = threadIdx.x;
    int h = tid >> 5;
    int lane = tid & 31;
    const unsigned FULL = 0xffffffffu;

    // ---- phase 1 (with inline softmax): one POINT per thread (tid < 128) ----
    if (tid < 128) {
        int jh = tid >> 4;          // head (16 consecutive threads per head)
        int p = tid & 15;           // point = l*4+pp
        int l = p >> 2;

        // inline softmax over the 16 points of this head (half-warp groups)
        float myl = __ldg(ol + (size_t)lq * 384 + 256 + jh * 16 + p);
        float mx = myl;
        #pragma unroll
        for (int o = 1; o <= 8; o <<= 1) mx = fmaxf(mx, __shfl_xor_sync(FULL, mx, o));
        float e = __expf(myl - mx);
        float s = e;
        #pragma unroll
        for (int o = 1; o <= 8; o <<= 1) s += __shfl_xor_sync(FULL, s, o);
        float aw = e / s;

        int Hl = __ldg(&shapes[l * 2 + 0]);
        int Wl = __ldg(&shapes[l * 2 + 1]);
        int st = __ldg(&starts[l]);
        float fW = (float)Wl, fH = (float)Hl;

        float rx = __ldg(&refp[(size_t)lq * 8 + l * 2 + 0]);
        float ry = __ldg(&refp[(size_t)lq * 8 + l * 2 + 1]);
        float2 oxy = __ldg(reinterpret_cast<const float2*>(ol + (size_t)lq * 384 + jh * 32 + p * 2));

        float x = rx * fW + oxy.x - 0.5f;
        float y = ry * fH + oxy.y - 0.5f;
        float x0f = floorf(x), y0f = floorf(y);
        float fx = x - x0f, fy = y - y0f;
        int x0 = (int)x0f, y0 = (int)y0f;

        float wx1 = fx * aw, wx0 = aw - wx1;
        float w00 = wx0 * (1.f - fy), w01 = wx1 * (1.f - fy);
        float w10 = wx0 * fy,         w11 = wx1 * fy;

        bool vx0 = (unsigned)x0 < (unsigned)Wl;
        bool vx1 = (unsigned)(x0 + 1) < (unsigned)Wl;
        bool vy0 = (unsigned)y0 < (unsigned)Hl;
        bool vy1 = (unsigned)(y0 + 1) < (unsigned)Hl;
        if (!(vx0 && vy0)) w00 = 0.f;
        if (!(vx1 && vy0)) w01 = 0.f;
        if (!(vx0 && vy1)) w10 = 0.f;
        if (!(vx1 && vy1)) w11 = 0.f;

        int xc0 = min(max(x0, 0), Wl - 1);
        int xc1 = min(max(x0 + 1, 0), Wl - 1);
        int yc0 = min(max(y0, 0), Hl - 1);
        int yc1 = min(max(y0 + 1, 0), Hl - 1);
        int base = st * 512 + jh * 64;
        int r0 = yc0 * Wl, r1 = yc1 * Wl;

        int4 e0, e1;
        e0.x = base + (r0 + xc0) * 512; e0.y = __float_as_int(w00);
        e0.z = base + (r0 + xc1) * 512; e0.w = __float_as_int(w01);
        e1.x = base + (r1 + xc0) * 512; e1.y = __float_as_int(w10);
        e1.z = base + (r1 + xc1) * 512; e1.w = __float_as_int(w11);
        int4* dst = reinterpret_cast<int4*>(&pw_s[tid * 4]);
        dst[0] = e0;
        dst[1] = e1;
    }
    __syncthreads();

    // ---- phase 2: 8 corners per LDG.128 round ----
    {
        const int2* pw = pw_s + h * 64;
        int cor = lane >> 2;
        int ch = lane & 3;
        const char* vbase = reinterpret_cast<const char*>(valh) + 16 * ch;
        int2 q[8];
        #pragma unroll
        for (int i = 0; i < 8; i++) q[i] = pw[i * 8 + cor];
        float a[8];
        #pragma unroll
        for (int i = 0; i < 8; i++) a[i] = 0.f;
        #pragma unroll
        for (int i = 0; i < 8; i++) {
            float w = __int_as_float(q[i].y);
            uint4 v = *reinterpret_cast<const uint4*>(vbase + q[i].x);
            float2 f0 = __bfloat1622float2(*reinterpret_cast<__nv_bfloat162*>(&v.x));
            float2 f1 = __bfloat1622float2(*reinterpret_cast<__nv_bfloat162*>(&v.y));
            float2 f2 = __bfloat1622float2(*reinterpret_cast<__nv_bfloat162*>(&v.z));
            float2 f3 = __bfloat1622float2(*reinterpret_cast<__nv_bfloat162*>(&v.w));
            a[0] += w * f0.x; a[1] += w * f0.y;
            a[2] += w * f1.x; a[3] += w * f1.y;
            a[4] += w * f2.x; a[5] += w * f2.y;
            a[6] += w * f3.x; a[7] += w * f3.y;
        }
        #pragma unroll
        for (int o = 4; o <= 16; o <<= 1)
            #pragma unroll
            for (int i = 0; i < 8; i++)
                a[i] += __shfl_xor_sync(FULL, a[i], o);
        if (lane < 4) {
            __nv_bfloat162 b0 = __floats2bfloat162_rn(a[0], a[1]);
            __nv_bfloat162 b1 = __floats2bfloat162_rn(a[2], a[3]);
            __nv_bfloat162 b2 = __floats2bfloat162_rn(a[4], a[5]);
            __nv_bfloat162 b3 = __floats2bfloat162_rn(a[6], a[7]);
            uint4 pk;
            pk.x = *reinterpret_cast<uint32_t*>(&b0);
            pk.y = *reinterpret_cast<uint32_t*>(&b1);
            pk.z = *reinterpret_cast<uint32_t*>(&b2);
            pk.w = *reinterpret_cast<uint32_t*>(&b3);
            *reinterpret_cast<uint4*>(acc + (size_t)lq * 256 + h * 32 + 8 * ch) = pk;
        }
    }
}

// ---------------- host ----------------
extern "C" void kernel_launch(void* const* d_in, const int* in_sizes, int n_in,
                              void* d_out, int out_size) {
    const float* query = (const float*)d_in[0];
    const float* refp  = (const float*)d_in[1];
    const float* pos   = (const float*)d_in[2];
    const int*   shp   = (const int*)d_in[3];
    const int*   sti   = (const int*)d_in[4];
    const float* w_off = (const float*)d_in[5];
    const float* b_off = (const float*)d_in[6];
    const float* w_attn= (const float*)d_in[7];
    const float* b_attn= (const float*)d_in[8];
    const float* w_val = (const float*)d_in[9];
    const float* b_val = (const float*)d_in[10];
    const float* w_out = (const float*)d_in[11];
    const float* b_out = (const float*)d_in[12];
    const float* g1    = (const float*)d_in[13];
    const float* be1   = (const float*)d_in[14];
    const float* w1    = (const float*)d_in[15];
    const float* b1    = (const float*)d_in[16];
    const float* w2    = (const float*)d_in[17];
    const float* b2    = (const float*)d_in[18];
    const float* g2    = (const float*)d_in[19];
    const float* be2   = (const float*)d_in[20];
    float* out = (float*)d_out;

    float *ol, *x, *bcat;
    __nv_bfloat16 *valh, *acch, *wvalh, *wouth, *w1h, *w2h, *wcath;
    cudaGetSymbolAddress((void**)&valh,  g_valh);
    cudaGetSymbolAddress((void**)&acch,  g_acch);
    cudaGetSymbolAddress((void**)&ol,    g_ol);
    cudaGetSymbolAddress((void**)&x,     g_x);
    cudaGetSymbolAddress((void**)&wvalh, g_wvalh);
    cudaGetSymbolAddress((void**)&wouth, g_wouth);
    cudaGetSymbolAddress((void**)&w1h,   g_w1h);
    cudaGetSymbolAddress((void**)&w2h,   g_w2h);
    cudaGetSymbolAddress((void**)&wcath, g_wcath);
    cudaGetSymbolAddress((void**)&bcat,  g_bcat);

    const int M = LQ;
    dim3 grid_n256(2, (M + 127) / 128);
    dim3 grid_n384(3, (M + 127) / 128);
    int grid_ln = (M + 63) / 64;

    cudaStream_t s1;
    cudaStreamCreateWithFlags(&s1, cudaStreamNonBlocking);
    cudaEvent_t e0, e1;
    cudaEventCreateWithFlags(&e0, cudaEventDisableTiming);
    cudaEventCreateWithFlags(&e1, cudaEventDisableTiming);

    pack_all<<<(360832 + 255) / 256, 256>>>(w_val, w_out, w1, w2, w_off, w_attn,
                                            b_off, b_attn,
                                            wvalh, wouth, w1h, w2h, wcath, bcat);

    cudaEventRecord(e0, 0);
    cudaStreamWaitEvent(s1, e0, 0);
    tgemm<<<grid_n256, 256, 0, s1>>>(query, nullptr, wvalh, b_val, valh, M, 256, 2);
    tgemm<<<grid_n384, 256>>>(query, pos, wcath, bcat, ol, M, 384, 0);

    cudaEventRecord(e1, s1);
    cudaStreamWaitEvent(0, e1, 0);

    sample_kernel<<<LQ, 256>>>(valh, refp, ol, shp, sti, acch);
    // x = LN(query + acc@w_out + b_out)
    tgemm_ln<<<grid_ln, 256>>>(acch, wouth, b_out, query, g1, be1, x, M);
    // out = LN(x + relu(x@w1+b1)@w2 + b2)   (fully fused FFN)
    tgemm_ffn<<<grid_ln, 256>>>(x, w1h, b1, w2h, b2, g2, be2, out, M);
}

// round 14
// speedup vs baseline: 1.3372x; 1.0443x over previous
#include <cuda_runtime.h>
#include <cuda_bf16.h>
#include <cstdint>

#define LQ 43054
#define D  256
#define NH 8
#define NL 4
#define NP 4
#define HD 32

// ---------------- scratch (device globals) ----------------
__device__ __nv_bfloat16 g_valh[LQ * D];
__device__ __nv_bfloat16 g_acch[LQ * D];
__device__ float g_ol  [LQ * 384];
__device__ float g_x   [LQ * D];
__device__ __nv_bfloat16 g_wvalh[256 * 256];
__device__ __nv_bfloat16 g_wouth[256 * 256];
__device__ __nv_bfloat16 g_w1h  [256 * 256];
__device__ __nv_bfloat16 g_w2h  [256 * 256];
__device__ __nv_bfloat16 g_wcath[256 * 384];
__device__ float g_bcat[384];

// ---------------- pack all weights to bf16 ----------------
__global__ void pack_all(const float* __restrict__ w_val, const float* __restrict__ w_out,
                         const float* __restrict__ w1, const float* __restrict__ w2,
                         const float* __restrict__ w_off, const float* __restrict__ w_attn,
                         const float* __restrict__ b_off, const float* __restrict__ b_attn,
                         __nv_bfloat16* __restrict__ wvalh, __nv_bfloat16* __restrict__ wouth,
                         __nv_bfloat16* __restrict__ w1h, __nv_bfloat16* __restrict__ w2h,
                         __nv_bfloat16* __restrict__ wcath, float* __restrict__ bcat) {
    int i = blockIdx.x * blockDim.x + threadIdx.x;
    if (i < 65536) { wvalh[i] = __float2bfloat16(w_val[i]); return; }
    i -= 65536;
    if (i < 65536) { wouth[i] = __float2bfloat16(w_out[i]); return; }
    i -= 65536;
    if (i < 65536) { w1h[i] = __float2bfloat16(w1[i]); return; }
    i -= 65536;
    if (i < 65536) { w2h[i] = __float2bfloat16(w2[i]); return; }
    i -= 65536;
    if (i < 98304) {
        int k = i / 384, n = i % 384;
        wcath[i] = __float2bfloat16(n < 256 ? w_off[k * 256 + n] : w_attn[k * 128 + (n - 256)]);
        return;
    }
    i -= 98304;
    if (i < 384) bcat[i] = (i < 256) ? b_off[i] : b_attn[i - 256];
}

// ---------------- bf16 tensor-core GEMM (BM=128 BN=128 BK=64) ----------------
// mode: 0 fp32 out, 2 bf16 out
__global__ __launch_bounds__(256, 2)
void tgemm(const float* __restrict__ A, const float* __restrict__ A2,
           const __nv_bfloat16* __restrict__ B,
           const float* __restrict__ bias, void* __restrict__ Cv,
           int M, int N, int mode) {
    constexpr int K = 256;
    constexpr int LDA = 72;
    constexpr int LDB = 136;
    __shared__ __align__(16) __nv_bfloat16 As[128 * LDA];
    __shared__ __align__(16) __nv_bfloat16 Bs[64 * LDB];

    int tid = threadIdx.x;
    int lane = tid & 31;
    int wid = tid >> 5;
    int bm = blockIdx.y * 128;
    int bn = blockIdx.x * 128;
    int wm = (wid >> 2) * 64;
    int wn = (wid & 3) * 32;

    float c[4][4][4];
    #pragma unroll
    for (int i = 0; i < 4; i++)
        #pragma unroll
        for (int j = 0; j < 4; j++)
            #pragma unroll
            for (int r = 0; r < 4; r++) c[i][j][r] = 0.f;

    int a_row = lane & 15;
    int a_koff = (lane >> 4) * 8;
    int b_krow = (lane & 7) + ((lane >> 3) & 1) * 8;
    int b_noff = (lane >> 4) * 8;

    for (int k0 = 0; k0 < K; k0 += 64) {
        #pragma unroll
        for (int i = 0; i < 8; i++) {
            int slot = tid + i * 256;
            int row = slot >> 4;
            int k4 = (slot & 15) * 4;
            float4 v = make_float4(0.f, 0.f, 0.f, 0.f);
            if (bm + row < M) {
                v = *reinterpret_cast<const float4*>(A + (size_t)(bm + row) * K + k0 + k4);
                if (A2) {
                    float4 u = *reinterpret_cast<const float4*>(A2 + (size_t)(bm + row) * K + k0 + k4);
                    v.x += u.x; v.y += u.y; v.z += u.z; v.w += u.w;
                }
            }
            __nv_bfloat162 p0 = __floats2bfloat162_rn(v.x, v.y);
            __nv_bfloat162 p1 = __floats2bfloat162_rn(v.z, v.w);
            uint2 st;
            st.x = *reinterpret_cast<uint32_t*>(&p0);
            st.y = *reinterpret_cast<uint32_t*>(&p1);
            *reinterpret_cast<uint2*>(&As[row * LDA + k4]) = st;
        }
        #pragma unroll
        for (int i = 0; i < 4; i++) {
            int slot = tid + i * 256;
            int kk = slot >> 4;
            int n8 = (slot & 15) * 8;
            uint4 v = *reinterpret_cast<const uint4*>(B + (size_t)(k0 + kk) * N + bn + n8);
            *reinterpret_cast<uint4*>(&Bs[kk * LDB + n8]) = v;
        }
        __syncthreads();

        #pragma unroll
        for (int ks = 0; ks < 4; ks++) {
            int kbase = ks * 16;
            uint32_t af[4][4];
            #pragma unroll
            for (int mf = 0; mf < 4; mf++) {
                const __nv_bfloat16* p = &As[(wm + mf * 16 + a_row) * LDA + kbase + a_koff];
                uint32_t addr = (uint32_t)__cvta_generic_to_shared(p);
                asm volatile("ldmatrix.sync.aligned.m8n8.x4.shared.b16 {%0,%1,%2,%3}, [%4];"
                             : "=r"(af[mf][0]), "=r"(af[mf][1]), "=r"(af[mf][2]), "=r"(af[mf][3])
                             : "r"(addr));
            }
            uint32_t bf[4][2];
            #pragma unroll
            for (int n16 = 0; n16 < 2; n16++) {
                const __nv_bfloat16* p = &Bs[(kbase + b_krow) * LDB + wn + n16 * 16 + b_noff];
                uint32_t addr = (uint32_t)__cvta_generic_to_shared(p);
                asm volatile("ldmatrix.sync.aligned.m8n8.x4.trans.shared.b16 {%0,%1,%2,%3}, [%4];"
                             : "=r"(bf[n16 * 2][0]), "=r"(bf[n16 * 2][1]),
                               "=r"(bf[n16 * 2 + 1][0]), "=r"(bf[n16 * 2 + 1][1])
                             : "r"(addr));
            }
            #pragma unroll
            for (int mf = 0; mf < 4; mf++)
                #pragma unroll
                for (int nf = 0; nf < 4; nf++) {
                    asm volatile(
                        "mma.sync.aligned.m16n8k16.row.col.f32.bf16.bf16.f32 "
                        "{%0,%1,%2,%3}, {%4,%5,%6,%7}, {%8,%9}, {%0,%1,%2,%3};"
                        : "+f"(c[mf][nf][0]), "+f"(c[mf][nf][1]),
                          "+f"(c[mf][nf][2]), "+f"(c[mf][nf][3])
                        : "r"(af[mf][0]), "r"(af[mf][1]), "r"(af[mf][2]), "r"(af[mf][3]),
                          "r"(bf[nf][0]), "r"(bf[nf][1]));
                }
        }
        __syncthreads();
    }

    #pragma unroll
    for (int mf = 0; mf < 4; mf++) {
        int row0 = bm + wm + mf * 16 + (lane >> 2);
        #pragma unroll
        for (int nf = 0; nf < 4; nf++) {
            int col = bn + wn + nf * 8 + (lane & 3) * 2;
            float bx = bias[col], by = bias[col + 1];
            float2 v0, v1;
            v0.x = c[mf][nf][0] + bx; v0.y = c[mf][nf][1] + by;
            v1.x = c[mf][nf][2] + bx; v1.y = c[mf][nf][3] + by;
            if (mode == 2) {
                __nv_bfloat16* C = (__nv_bfloat16*)Cv;
                if (row0 < M)
                    *reinterpret_cast<__nv_bfloat162*>(C + (size_t)row0 * N + col) =
                        __floats2bfloat162_rn(v0.x, v0.y);
                if (row0 + 8 < M)
                    *reinterpret_cast<__nv_bfloat162*>(C + (size_t)(row0 + 8) * N + col) =
                        __floats2bfloat162_rn(v1.x, v1.y);
            } else {
                float* C = (float*)Cv;
                if (row0 < M)
                    *reinterpret_cast<float2*>(C + (size_t)row0 * N + col) = v0;
                if (row0 + 8 < M)
                    *reinterpret_cast<float2*>(C + (size_t)(row0 + 8) * N + col) = v1;
            }
        }
    }
}

// ---------------- bf16 GEMM + residual + LayerNorm fused (A bf16, B bf16) ----
__global__ __launch_bounds__(256)
void tgemm_ln(const __nv_bfloat16* __restrict__ A, const __nv_bfloat16* __restrict__ B,
              const float* __restrict__ bias, const float* __restrict__ res,
              const float* __restrict__ gam, const float* __restrict__ bet,
              float* __restrict__ out, int M) {
    constexpr int K = 256;
    constexpr int N = 256;
    constexpr int LDA = 72;
    constexpr int LDB = 264;
    __shared__ __align__(16) __nv_bfloat16 As[64 * LDA];
    __shared__ __align__(16) __nv_bfloat16 Bs[64 * LDB];
    __shared__ float rsum[4][64];
    __shared__ float rsq[4][64];

    int tid = threadIdx.x;
    int lane = tid & 31;
    int wid = tid >> 5;
    int bm = blockIdx.x * 64;
    int wm = (wid >> 2) * 32;
    int wn = (wid & 3) * 64;

    float c[2][8][4];
    #pragma unroll
    for (int i = 0; i < 2; i++)
        #pragma unroll
        for (int j = 0; j < 8; j++)
            #pragma unroll
            for (int r = 0; r < 4; r++) c[i][j][r] = 0.f;

    int a_row = lane & 15;
    int a_koff = (lane >> 4) * 8;
    int b_krow = (lane & 7) + ((lane >> 3) & 1) * 8;
    int b_noff = (lane >> 4) * 8;

    for (int k0 = 0; k0 < K; k0 += 64) {
        #pragma unroll
        for (int i = 0; i < 2; i++) {
            int slot = tid + i * 256;
            int row = slot >> 3;
            int k8 = (slot & 7) * 8;
            uint4 v = make_uint4(0, 0, 0, 0);
            if (bm + row < M)
                v = *reinterpret_cast<const uint4*>(A + (size_t)(bm + row) * K + k0 + k8);
            *reinterpret_cast<uint4*>(&As[row * LDA + k8]) = v;
        }
        #pragma unroll
        for (int i = 0; i < 8; i++) {
            int slot = tid + i * 256;
            int kk = slot >> 5;
            int n8 = (slot & 31) * 8;
            uint4 v = *reinterpret_cast<const uint4*>(B + (size_t)(k0 + kk) * N + n8);
            *reinterpret_cast<uint4*>(&Bs[kk * LDB + n8]) = v;
        }
        __syncthreads();

        #pragma unroll
        for (int ks = 0; ks < 4; ks++) {
            int kbase = ks * 16;
            uint32_t af[2][4];
            #pragma unroll
            for (int mf = 0; mf < 2; mf++) {
                const __nv_bfloat16* p = &As[(wm + mf * 16 + a_row) * LDA + kbase + a_koff];
                uint32_t addr = (uint32_t)__cvta_generic_to_shared(p);
                asm volatile("ldmatrix.sync.aligned.m8n8.x4.shared.b16 {%0,%1,%2,%3}, [%4];"
                             : "=r"(af[mf][0]), "=r"(af[mf][1]), "=r"(af[mf][2]), "=r"(af[mf][3])
                             : "r"(addr));
            }
            uint32_t bf[8][2];
            #pragma unroll
            for (int n16 = 0; n16 < 4; n16++) {
                const __nv_bfloat16* p = &Bs[(kbase + b_krow) * LDB + wn + n16 * 16 + b_noff];
                uint32_t addr = (uint32_t)__cvta_generic_to_shared(p);
                asm volatile("ldmatrix.sync.aligned.m8n8.x4.trans.shared.b16 {%0,%1,%2,%3}, [%4];"
                             : "=r"(bf[n16 * 2][0]), "=r"(bf[n16 * 2][1]),
                               "=r"(bf[n16 * 2 + 1][0]), "=r"(bf[n16 * 2 + 1][1])
                             : "r"(addr));
            }
            #pragma unroll
            for (int mf = 0; mf < 2; mf++)
                #pragma unroll
                for (int nf = 0; nf < 8; nf++) {
                    asm volatile(
                        "mma.sync.aligned.m16n8k16.row.col.f32.bf16.bf16.f32 "
                        "{%0,%1,%2,%3}, {%4,%5,%6,%7}, {%8,%9}, {%0,%1,%2,%3};"
                        : "+f"(c[mf][nf][0]), "+f"(c[mf][nf][1]),
                          "+f"(c[mf][nf][2]), "+f"(c[mf][nf][3])
                        : "r"(af[mf][0]), "r"(af[mf][1]), "r"(af[mf][2]), "r"(af[mf][3]),
                          "r"(bf[nf][0]), "r"(bf[nf][1]));
                }
        }
        __syncthreads();
    }

    float sums[2][2] = {{0.f, 0.f}, {0.f, 0.f}};
    float sqs [2][2] = {{0.f, 0.f}, {0.f, 0.f}};
    #pragma unroll
    for (int mf = 0; mf < 2; mf++) {
        int row0 = bm + wm + mf * 16 + (lane >> 2);
        int row1 = row0 + 8;
        #pragma unroll
        for (int nf = 0; nf < 8; nf++) {
            int col = wn + nf * 8 + (lane & 3) * 2;
            float bx = __ldg(bias + col), by = __ldg(bias + col + 1);
            float2 r0 = make_float2(0.f, 0.f), r1 = make_float2(0.f, 0.f);
            if (row0 < M) r0 = *reinterpret_cast<const float2*>(res + (size_t)row0 * N + col);
            if (row1 < M) r1 = *reinterpret_cast<const float2*>(res + (size_t)row1 * N + col);
            float v0x = c[mf][nf][0] + bx + r0.x;
            float v0y = c[mf][nf][1] + by + r0.y;
            float v1x = c[mf][nf][2] + bx + r1.x;
            float v1y = c[mf][nf][3] + by + r1.y;
            c[mf][nf][0] = v0x; c[mf][nf][1] = v0y;
            c[mf][nf][2] = v1x; c[mf][nf][3] = v1y;
            sums[mf][0] += v0x + v0y;
            sqs [mf][0] += v0x * v0x + v0y * v0y;
            sums[mf][1] += v1x + v1y;
            sqs [mf][1] += v1x * v1x + v1y * v1y;
        }
    }
    #pragma unroll
    for (int o = 1; o <= 2; o <<= 1) {
        #pragma unroll
        for (int mf = 0; mf < 2; mf++)
            #pragma unroll
            for (int hf = 0; hf < 2; hf++) {
                sums[mf][hf] += __shfl_xor_sync(0xffffffffu, sums[mf][hf], o);
                sqs [mf][hf] += __shfl_xor_sync(0xffffffffu, sqs [mf][hf], o);
            }
    }
    if ((lane & 3) == 0) {
        #pragma unroll
        for (int mf = 0; mf < 2; mf++)
            #pragma unroll
            for (int hf = 0; hf < 2; hf++) {
                int rl = wm + mf * 16 + (lane >> 2) + 8 * hf;
                rsum[wid & 3][rl] = sums[mf][hf];
                rsq [wid & 3][rl] = sqs [mf][hf];
            }
    }
    __syncthreads();

    #pragma unroll
    for (int mf = 0; mf < 2; mf++) {
        int rl0 = wm + mf * 16 + (lane >> 2);
        int rl1 = rl0 + 8;
        float s0 = rsum[0][rl0] + rsum[1][rl0] + rsum[2][rl0] + rsum[3][rl0];
        float q0 = rsq [0][rl0] + rsq [1][rl0] + rsq [2][rl0] + rsq [3][rl0];
        float s1 = rsum[0][rl1] + rsum[1][rl1] + rsum[2][rl1] + rsum[3][rl1];
        float q1 = rsq [0][rl1] + rsq [1][rl1] + rsq [2][rl1] + rsq [3][rl1];
        float m0 = s0 * (1.f / 256.f);
        float m1 = s1 * (1.f / 256.f);
        float rs0 = rsqrtf(fmaxf(q0 * (1.f / 256.f) - m0 * m0, 0.f) + 1e-5f);
        float rs1 = rsqrtf(fmaxf(q1 * (1.f / 256.f) - m1 * m1, 0.f) + 1e-5f);
        int row0 = bm + rl0;
        int row1 = bm + rl1;
        #pragma unroll
        for (int nf = 0; nf < 8; nf++) {
            int col = wn + nf * 8 + (lane & 3) * 2;
            float gx = __ldg(gam + col), gy = __ldg(gam + col + 1);
            float bx = __ldg(bet + col), by = __ldg(bet + col + 1);
            if (row0 < M) {
                float2 o0;
                o0.x = (c[mf][nf][0] - m0) * rs0 * gx + bx;
                o0.y = (c[mf][nf][1] - m0) * rs0 * gy + by;
                *reinterpret_cast<float2*>(out + (size_t)row0 * N + col) = o0;
            }
            if (row1 < M) {
                float2 o1;
                o1.x = (c[mf][nf][2] - m1) * rs1 * gx + bx;
                o1.y = (c[mf][nf][3] - m1) * rs1 * gy + by;
                *reinterpret_cast<float2*>(out + (size_t)row1 * N + col) = o1;
            }
        }
    }
}

// ---------------- fused FFN: out = LN(x + relu(x@W1+b1)@W2+b2) ----------------
__global__ __launch_bounds__(256)
void tgemm_ffn(const float* __restrict__ X,
               const __nv_bfloat16* __restrict__ W1, const float* __restrict__ b1,
               const __nv_bfloat16* __restrict__ W2, const float* __restrict__ b2,
               const float* __restrict__ gam, const float* __restrict__ bet,
               float* __restrict__ out, int M) {
    constexpr int K = 256;
    constexpr int N = 256;
    constexpr int LDA = 72;
    constexpr int LDB = 264;
    constexpr int LDH = 264;
    __shared__ __align__(16) __nv_bfloat16 As[64 * LDA];
    __shared__ __align__(16) __nv_bfloat16 Bs[64 * LDB];
    __shared__ __align__(16) __nv_bfloat16 Hs[64 * LDH];
    __shared__ float rsum[4][64];
    __shared__ float rsq[4][64];

    int tid = threadIdx.x;
    int lane = tid & 31;
    int wid = tid >> 5;
    int bm = blockIdx.x * 64;
    int wm = (wid >> 2) * 32;
    int wn = (wid & 3) * 64;

    int a_row = lane & 15;
    int a_koff = (lane >> 4) * 8;
    int b_krow = (lane & 7) + ((lane >> 3) & 1) * 8;
    int b_noff = (lane >> 4) * 8;

    float c[2][8][4];

    #pragma unroll
    for (int i = 0; i < 2; i++)
        #pragma unroll
        for (int j = 0; j < 8; j++)
            #pragma unroll
            for (int r = 0; r < 4; r++) c[i][j][r] = 0.f;

    for (int k0 = 0; k0 < K; k0 += 64) {
        #pragma unroll
        for (int i = 0; i < 4; i++) {
            int slot = tid + i * 256;
            int row = slot >> 4;
            int k4 = (slot & 15) * 4;
            float4 v = make_float4(0.f, 0.f, 0.f, 0.f);
            if (bm + row < M)
                v = *reinterpret_cast<const float4*>(X + (size_t)(bm + row) * K + k0 + k4);
            __nv_bfloat162 p0 = __floats2bfloat162_rn(v.x, v.y);
            __nv_bfloat162 p1 = __floats2bfloat162_rn(v.z, v.w);
            uint2 st;
            st.x = *reinterpret_cast<uint32_t*>(&p0);
            st.y = *reinterpret_cast<uint32_t*>(&p1);
            *reinterpret_cast<uint2*>(&As[row * LDA + k4]) = st;
        }
        #pragma unroll
        for (int i = 0; i < 8; i++) {
            int slot = tid + i * 256;
            int kk = slot >> 5;
            int n8 = (slot & 31) * 8;
            uint4 v = *reinterpret_cast<const uint4*>(W1 + (size_t)(k0 + kk) * N + n8);
            *reinterpret_cast<uint4*>(&Bs[kk * LDB + n8]) = v;
        }
        __syncthreads();

        #pragma unroll
        for (int ks = 0; ks < 4; ks++) {
            int kbase = ks * 16;
            uint32_t af[2][4];
            #pragma unroll
            for (int mf = 0; mf < 2; mf++) {
                const __nv_bfloat16* p = &As[(wm + mf * 16 + a_row) * LDA + kbase + a_koff];
                uint32_t addr = (uint32_t)__cvta_generic_to_shared(p);
                asm volatile("ldmatrix.sync.aligned.m8n8.x4.shared.b16 {%0,%1,%2,%3}, [%4];"
                             : "=r"(af[mf][0]), "=r"(af[mf][1]), "=r"(af[mf][2]), "=r"(af[mf][3])
                             : "r"(addr));
            }
            uint32_t bf[8][2];
            #pragma unroll
            for (int n16 = 0; n16 < 4; n16++) {
                const __nv_bfloat16* p = &Bs[(kbase + b_krow) * LDB + wn + n16 * 16 + b_noff];
                uint32_t addr = (uint32_t)__cvta_generic_to_shared(p);
                asm volatile("ldmatrix.sync.aligned.m8n8.x4.trans.shared.b16 {%0,%1,%2,%3}, [%4];"
                             : "=r"(bf[n16 * 2][0]), "=r"(bf[n16 * 2][1]),
                               "=r"(bf[n16 * 2 + 1][0]), "=r"(bf[n16 * 2 + 1][1])
                             : "r"(addr));
            }
            #pragma unroll
            for (int mf = 0; mf < 2; mf++)
                #pragma unroll
                for (int nf = 0; nf < 8; nf++) {
                    asm volatile(
                        "mma.sync.aligned.m16n8k16.row.col.f32.bf16.bf16.f32 "
                        "{%0,%1,%2,%3}, {%4,%5,%6,%7}, {%8,%9}, {%0,%1,%2,%3};"
                        : "+f"(c[mf][nf][0]), "+f"(c[mf][nf][1]),
                          "+f"(c[mf][nf][2]), "+f"(c[mf][nf][3])
                        : "r"(af[mf][0]), "r"(af[mf][1]), "r"(af[mf][2]), "r"(af[mf][3]),
                          "r"(bf[nf][0]), "r"(bf[nf][1]));
                }
        }
        __syncthreads();
    }

    #pragma unroll
    for (int mf = 0; mf < 2; mf++) {
        int rl0 = wm + mf * 16 + (lane >> 2);
        int rl1 = rl0 + 8;
        #pragma unroll
        for (int nf = 0; nf < 8; nf++) {
            int col = wn + nf * 8 + (lane & 3) * 2;
            float bx = __ldg(b1 + col), by = __ldg(b1 + col + 1);
            float h0x = fmaxf(c[mf][nf][0] + bx, 0.f);
            float h0y = fmaxf(c[mf][nf][1] + by, 0.f);
            float h1x = fmaxf(c[mf][nf][2] + bx, 0.f);
            float h1y = fmaxf(c[mf][nf][3] + by, 0.f);
            __nv_bfloat162 p0 = __floats2bfloat162_rn(h0x, h0y);
            __nv_bfloat162 p1 = __floats2bfloat162_rn(h1x, h1y);
            *reinterpret_cast<__nv_bfloat162*>(&Hs[rl0 * LDH + col]) = p0;
            *reinterpret_cast<__nv_bfloat162*>(&Hs[rl1 * LDH + col]) = p1;
        }
    }
    __syncthreads();

    #pragma unroll
    for (int i = 0; i < 2; i++)
        #pragma unroll
        for (int j = 0; j < 8; j++)
            #pragma unroll
            for (int r = 0; r < 4; r++) c[i][j][r] = 0.f;

    for (int k0 = 0; k0 < K; k0 += 64) {
        #pragma unroll
        for (int i = 0; i < 8; i++) {
            int slot = tid + i * 256;
            int kk = slot >> 5;
            int n8 = (slot & 31) * 8;
            uint4 v = *reinterpret_cast<const uint4*>(W2 + (size_t)(k0 + kk) * N + n8);
            *reinterpret_cast<uint4*>(&Bs[kk * LDB + n8]) = v;
        }
        __syncthreads();

        #pragma unroll
        for (int ks = 0; ks < 4; ks++) {
            int kbase = k0 + ks * 16;
            uint32_t af[2][4];
            #pragma unroll
            for (int mf = 0; mf < 2; mf++) {
                const __nv_bfloat16* p = &Hs[(wm + mf * 16 + a_row) * LDH + kbase + a_koff];
                uint32_t addr = (uint32_t)__cvta_generic_to_shared(p);
                asm volatile("ldmatrix.sync.aligned.m8n8.x4.shared.b16 {%0,%1,%2,%3}, [%4];"
                             : "=r"(af[mf][0]), "=r"(af[mf][1]), "=r"(af[mf][2]), "=r"(af[mf][3])
                             : "r"(addr));
            }
            uint32_t bf[8][2];
            #pragma unroll
            for (int n16 = 0; n16 < 4; n16++) {
                const __nv_bfloat16* p = &Bs[((ks * 16) + b_krow) * LDB + wn + n16 * 16 + b_noff];
                uint32_t addr = (uint32_t)__cvta_generic_to_shared(p);
                asm volatile("ldmatrix.sync.aligned.m8n8.x4.trans.shared.b16 {%0,%1,%2,%3}, [%4];"
                             : "=r"(bf[n16 * 2][0]), "=r"(bf[n16 * 2][1]),
                               "=r"(bf[n16 * 2 + 1][0]), "=r"(bf[n16 * 2 + 1][1])
                             : "r"(addr));
            }
            #pragma unroll
            for (int mf = 0; mf < 2; mf++)
                #pragma unroll
                for (int nf = 0; nf < 8; nf++) {
                    asm volatile(
                        "mma.sync.aligned.m16n8k16.row.col.f32.bf16.bf16.f32 "
                        "{%0,%1,%2,%3}, {%4,%5,%6,%7}, {%8,%9}, {%0,%1,%2,%3};"
                        : "+f"(c[mf][nf][0]), "+f"(c[mf][nf][1]),
                          "+f"(c[mf][nf][2]), "+f"(c[mf][nf][3])
                        : "r"(af[mf][0]), "r"(af[mf][1]), "r"(af[mf][2]), "r"(af[mf][3]),
                          "r"(bf[nf][0]), "r"(bf[nf][1]));
                }
        }
        __syncthreads();
    }

    float sums[2][2] = {{0.f, 0.f}, {0.f, 0.f}};
    float sqs [2][2] = {{0.f, 0.f}, {0.f, 0.f}};
    #pragma unroll
    for (int mf = 0; mf < 2; mf++) {
        int row0 = bm + wm + mf * 16 + (lane >> 2);
        int row1 = row0 + 8;
        #pragma unroll
        for (int nf = 0; nf < 8; nf++) {
            int col = wn + nf * 8 + (lane & 3) * 2;
            float bx = __ldg(b2 + col), by = __ldg(b2 + col + 1);
            float2 r0 = make_float2(0.f, 0.f), r1 = make_float2(0.f, 0.f);
            if (row0 < M) r0 = *reinterpret_cast<const float2*>(X + (size_t)row0 * N + col);
            if (row1 < M) r1 = *reinterpret_cast<const float2*>(X + (size_t)row1 * N + col);
            float v0x = c[mf][nf][0] + bx + r0.x;
            float v0y = c[mf][nf][1] + by + r0.y;
            float v1x = c[mf][nf][2] + bx + r1.x;
            float v1y = c[mf][nf][3] + by + r1.y;
            c[mf][nf][0] = v0x; c[mf][nf][1] = v0y;
            c[mf][nf][2] = v1x; c[mf][nf][3] = v1y;
            sums[mf][0] += v0x + v0y;
            sqs [mf][0] += v0x * v0x + v0y * v0y;
            sums[mf][1] += v1x + v1y;
            sqs [mf][1] += v1x * v1x + v1y * v1y;
        }
    }
    #pragma unroll
    for (int o = 1; o <= 2; o <<= 1) {
        #pragma unroll
        for (int mf = 0; mf < 2; mf++)
            #pragma unroll
            for (int hf = 0; hf < 2; hf++) {
                sums[mf][hf] += __shfl_xor_sync(0xffffffffu, sums[mf][hf], o);
                sqs [mf][hf] += __shfl_xor_sync(0xffffffffu, sqs [mf][hf], o);
            }
    }
    if ((lane & 3) == 0) {
        #pragma unroll
        for (int mf = 0; mf < 2; mf++)
            #pragma unroll
            for (int hf = 0; hf < 2; hf++) {
                int rl = wm + mf * 16 + (lane >> 2) + 8 * hf;
                rsum[wid & 3][rl] = sums[mf][hf];
                rsq [wid & 3][rl] = sqs [mf][hf];
            }
    }
    __syncthreads();

    #pragma unroll
    for (int mf = 0; mf < 2; mf++) {
        int rl0 = wm + mf * 16 + (lane >> 2);
        int rl1 = rl0 + 8;
        float s0 = rsum[0][rl0] + rsum[1][rl0] + rsum[2][rl0] + rsum[3][rl0];
        float q0 = rsq [0][rl0] + rsq [1][rl0] + rsq [2][rl0] + rsq [3][rl0];
        float s1 = rsum[0][rl1] + rsum[1][rl1] + rsum[2][rl1] + rsum[3][rl1];
        float q1 = rsq [0][rl1] + rsq [1][rl1] + rsq [2][rl1] + rsq [3][rl1];
        float m0 = s0 * (1.f / 256.f);
        float m1 = s1 * (1.f / 256.f);
        float rs0 = rsqrtf(fmaxf(q0 * (1.f / 256.f) - m0 * m0, 0.f) + 1e-5f);
        float rs1 = rsqrtf(fmaxf(q1 * (1.f / 256.f) - m1 * m1, 0.f) + 1e-5f);
        int row0 = bm + rl0;
        int row1 = bm + rl1;
        #pragma unroll
        for (int nf = 0; nf < 8; nf++) {
            int col = wn + nf * 8 + (lane & 3) * 2;
            float gx = __ldg(gam + col), gy = __ldg(gam + col + 1);
            float bx = __ldg(bet + col), by = __ldg(bet + col + 1);
            if (row0 < M) {
                float2 o0;
                o0.x = (c[mf][nf][0] - m0) * rs0 * gx + bx;
                o0.y = (c[mf][nf][1] - m0) * rs0 * gy + by;
                *reinterpret_cast<float2*>(out + (size_t)row0 * N + col) = o0;
            }
            if (row1 < M) {
                float2 o1;
                o1.x = (c[mf][nf][2] - m1) * rs1 * gx + bx;
                o1.y = (c[mf][nf][3] - m1) * rs1 * gy + by;
                *reinterpret_cast<float2*>(out + (size_t)row1 * N + col) = o1;
            }
        }
    }
}

// ---------------- deformable sampling: 2 queries per CTA ----------
__global__ __launch_bounds__(256)
void sample_kernel(const __nv_bfloat16* __restrict__ valh,
                   const float* __restrict__ refp,
                   const float* __restrict__ ol,
                   const int* __restrict__ shapes,
                   const int* __restrict__ starts,
                   __nv_bfloat16* __restrict__ acc,
                   int nq) {
    __shared__ __align__(16) int2 pw_s[1024];   // 2 queries x 512 corners

    int lq0 = blockIdx.x * 2;
    int tid = threadIdx.x;
    int h = tid >> 5;
    int lane = tid & 31;
    const unsigned FULL = 0xffffffffu;

    // ---- phase 1: all 256 threads; thread = (query, head, point) ----
    {
        int lq = lq0 + (tid >> 7);           // query
        int jh = (tid >> 4) & 7;             // head
        int p = tid & 15;                    // point = l*4+pp
        int l = p >> 2;
        bool qvalid = lq < nq;
        size_t olbase = (size_t)min(lq, nq - 1) * 384;

        // inline softmax over 16-thread group
        float myl = __ldg(ol + olbase + 256 + jh * 16 + p);
        float mx = myl;
        #pragma unroll
        for (int o = 1; o <= 8; o <<= 1) mx = fmaxf(mx, __shfl_xor_sync(FULL, mx, o));
        float e = __expf(myl - mx);
        float s = e;
        #pragma unroll
        for (int o = 1; o <= 8; o <<= 1) s += __shfl_xor_sync(FULL, s, o);
        float aw = e / s;

        int Hl = __ldg(&shapes[l * 2 + 0]);
        int Wl = __ldg(&shapes[l * 2 + 1]);
        int st = __ldg(&starts[l]);
        float fW = (float)Wl, fH = (float)Hl;

        float rx = __ldg(&refp[(size_t)min(lq, nq - 1) * 8 + l * 2 + 0]);
        float ry = __ldg(&refp[(size_t)min(lq, nq - 1) * 8 + l * 2 + 1]);
        float2 oxy = __ldg(reinterpret_cast<const float2*>(ol + olbase + jh * 32 + p * 2));

        float x = rx * fW + oxy.x - 0.5f;
        float y = ry * fH + oxy.y - 0.5f;
        float x0f = floorf(x), y0f = floorf(y);
        float fx = x - x0f, fy = y - y0f;
        int x0 = (int)x0f, y0 = (int)y0f;

        float wx1 = fx * aw, wx0 = aw - wx1;
        float w00 = wx0 * (1.f - fy), w01 = wx1 * (1.f - fy);
        float w10 = wx0 * fy,         w11 = wx1 * fy;

        bool vx0 = (unsigned)x0 < (unsigned)Wl;
        bool vx1 = (unsigned)(x0 + 1) < (unsigned)Wl;
        bool vy0 = (unsigned)y0 < (unsigned)Hl;
        bool vy1 = (unsigned)(y0 + 1) < (unsigned)Hl;
        if (!(vx0 && vy0) || !qvalid) w00 = 0.f;
        if (!(vx1 && vy0) || !qvalid) w01 = 0.f;
        if (!(vx0 && vy1) || !qvalid) w10 = 0.f;
        if (!(vx1 && vy1) || !qvalid) w11 = 0.f;

        int xc0 = min(max(x0, 0), Wl - 1);
        int xc1 = min(max(x0 + 1, 0), Wl - 1);
        int yc0 = min(max(y0, 0), Hl - 1);
        int yc1 = min(max(y0 + 1, 0), Hl - 1);
        int base = st * 512 + jh * 64;
        int r0 = yc0 * Wl, r1 = yc1 * Wl;

        int4 e0, e1;
        e0.x = base + (r0 + xc0) * 512; e0.y = __float_as_int(w00);
        e0.z = base + (r0 + xc1) * 512; e0.w = __float_as_int(w01);
        e1.x = base + (r1 + xc0) * 512; e1.y = __float_as_int(w10);
        e1.z = base + (r1 + xc1) * 512; e1.w = __float_as_int(w11);
        int4* dst = reinterpret_cast<int4*>(&pw_s[tid * 4]);
        dst[0] = e0;
        dst[1] = e1;
    }
    __syncthreads();

    // ---- phase 2: warp h gathers head h for both queries ----
    {
        int cor = lane >> 2;
        int ch = lane & 3;
        const char* vbase = reinterpret_cast<const char*>(valh) + 16 * ch;
        #pragma unroll
        for (int q = 0; q < 2; q++) {
            int lq = lq0 + q;
            if (lq >= nq) break;
            const int2* pw = pw_s + q * 512 + h * 64;
            int2 qr[8];
            #pragma unroll
            for (int i = 0; i < 8; i++) qr[i] = pw[i * 8 + cor];
            float a[8];
            #pragma unroll
            for (int i = 0; i < 8; i++) a[i] = 0.f;
            #pragma unroll
            for (int i = 0; i < 8; i++) {
                float w = __int_as_float(qr[i].y);
                uint4 v = *reinterpret_cast<const uint4*>(vbase + qr[i].x);
                float2 f0 = __bfloat1622float2(*reinterpret_cast<__nv_bfloat162*>(&v.x));
                float2 f1 = __bfloat1622float2(*reinterpret_cast<__nv_bfloat162*>(&v.y));
                float2 f2 = __bfloat1622float2(*reinterpret_cast<__nv_bfloat162*>(&v.z));
                float2 f3 = __bfloat1622float2(*reinterpret_cast<__nv_bfloat162*>(&v.w));
                a[0] += w * f0.x; a[1] += w * f0.y;
                a[2] += w * f1.x; a[3] += w * f1.y;
                a[4] += w * f2.x; a[5] += w * f2.y;
                a[6] += w * f3.x; a[7] += w * f3.y;
            }
            #pragma unroll
            for (int o = 4; o <= 16; o <<= 1)
                #pragma unroll
                for (int i = 0; i < 8; i++)
                    a[i] += __shfl_xor_sync(FULL, a[i], o);
            if (lane < 4) {
                __nv_bfloat162 b0 = __floats2bfloat162_rn(a[0], a[1]);
                __nv_bfloat162 b1 = __floats2bfloat162_rn(a[2], a[3]);
                __nv_bfloat162 b2 = __floats2bfloat162_rn(a[4], a[5]);
                __nv_bfloat162 b3 = __floats2bfloat162_rn(a[6], a[7]);
                uint4 pk;
                pk.x = *reinterpret_cast<uint32_t*>(&b0);
                pk.y = *reinterpret_cast<uint32_t*>(&b1);
                pk.z = *reinterpret_cast<uint32_t*>(&b2);
                pk.w = *reinterpret_cast<uint32_t*>(&b3);
                *reinterpret_cast<uint4*>(acc + (size_t)lq * 256 + h * 32 + 8 * ch) = pk;
            }
        }
    }
}

// ---------------- host ----------------
extern "C" void kernel_launch(void* const* d_in, const int* in_sizes, int n_in,
                              void* d_out, int out_size) {
    const float* query = (const float*)d_in[0];
    const float* refp  = (const float*)d_in[1];
    const float* pos   = (const float*)d_in[2];
    const int*   shp   = (const int*)d_in[3];
    const int*   sti   = (const int*)d_in[4];
    const float* w_off = (const float*)d_in[5];
    const float* b_off = (const float*)d_in[6];
    const float* w_attn= (const float*)d_in[7];
    const float* b_attn= (const float*)d_in[8];
    const float* w_val = (const float*)d_in[9];
    const float* b_val = (const float*)d_in[10];
    const float* w_out = (const float*)d_in[11];
    const float* b_out = (const float*)d_in[12];
    const float* g1    = (const float*)d_in[13];
    const float* be1   = (const float*)d_in[14];
    const float* w1    = (const float*)d_in[15];
    const float* b1    = (const float*)d_in[16];
    const float* w2    = (const float*)d_in[17];
    const float* b2    = (const float*)d_in[18];
    const float* g2    = (const float*)d_in[19];
    const float* be2   = (const float*)d_in[20];
    float* out = (float*)d_out;

    float *ol, *x, *bcat;
    __nv_bfloat16 *valh, *acch, *wvalh, *wouth, *w1h, *w2h, *wcath;
    cudaGetSymbolAddress((void**)&valh,  g_valh);
    cudaGetSymbolAddress((void**)&acch,  g_acch);
    cudaGetSymbolAddress((void**)&ol,    g_ol);
    cudaGetSymbolAddress((void**)&x,     g_x);
    cudaGetSymbolAddress((void**)&wvalh, g_wvalh);
    cudaGetSymbolAddress((void**)&wouth, g_wouth);
    cudaGetSymbolAddress((void**)&w1h,   g_w1h);
    cudaGetSymbolAddress((void**)&w2h,   g_w2h);
    cudaGetSymbolAddress((void**)&wcath, g_wcath);
    cudaGetSymbolAddress((void**)&bcat,  g_bcat);

    const int M = LQ;
    dim3 grid_n256(2, (M + 127) / 128);
    dim3 grid_n384(3, (M + 127) / 128);
    int grid_ln = (M + 63) / 64;
    int grid_smp = (M + 1) / 2;

    cudaStream_t s1;
    cudaStreamCreateWithFlags(&s1, cudaStreamNonBlocking);
    cudaEvent_t e0, e1;
    cudaEventCreateWithFlags(&e0, cudaEventDisableTiming);
    cudaEventCreateWithFlags(&e1, cudaEventDisableTiming);

    pack_all<<<(360832 + 255) / 256, 256>>>(w_val, w_out, w1, w2, w_off, w_attn,
                                            b_off, b_attn,
                                            wvalh, wouth, w1h, w2h, wcath, bcat);

    cudaEventRecord(e0, 0);
    cudaStreamWaitEvent(s1, e0, 0);
    tgemm<<<grid_n256, 256, 0, s1>>>(query, nullptr, wvalh, b_val, valh, M, 256, 2);
    tgemm<<<grid_n384, 256>>>(query, pos, wcath, bcat, ol, M, 384, 0);

    cudaEventRecord(e1, s1);
    cudaStreamWaitEvent(0, e1, 0);

    sample_kernel<<<grid_smp, 256>>>(valh, refp, ol, shp, sti, acch, M);
    tgemm_ln<<<grid_ln, 256>>>(acch, wouth, b_out, query, g1, be1, x, M);
    tgemm_ffn<<<grid_ln, 256>>>(x, w1h, b1, w2h, b2, g2, be2, out, M);
}

// round 15
// speedup vs baseline: 1.4058x; 1.0513x over previous
#include <cuda_runtime.h>
#include <cuda_bf16.h>
#include <cstdint>

#define LQ 43054
#define D  256
#define NH 8
#define NL 4
#define NP 4
#define HD 32

// ---------------- scratch (device globals) ----------------
__device__ __nv_bfloat16 g_valh[LQ * D];
__device__ __nv_bfloat16 g_acch[LQ * D];
__device__ float g_ol  [LQ * 384];
__device__ float g_x   [LQ * D];
__device__ __nv_bfloat16 g_wvalh[256 * 256];
__device__ __nv_bfloat16 g_wouth[256 * 256];
__device__ __nv_bfloat16 g_w1h  [256 * 256];
__device__ __nv_bfloat16 g_w2h  [256 * 256];
__device__ __nv_bfloat16 g_wcath[256 * 384];
__device__ float g_bcat[384];

// ---------------- pack all weights to bf16 ----------------
__global__ void pack_all(const float* __restrict__ w_val, const float* __restrict__ w_out,
                         const float* __restrict__ w1, const float* __restrict__ w2,
                         const float* __restrict__ w_off, const float* __restrict__ w_attn,
                         const float* __restrict__ b_off, const float* __restrict__ b_attn,
                         __nv_bfloat16* __restrict__ wvalh, __nv_bfloat16* __restrict__ wouth,
                         __nv_bfloat16* __restrict__ w1h, __nv_bfloat16* __restrict__ w2h,
                         __nv_bfloat16* __restrict__ wcath, float* __restrict__ bcat) {
    int i = blockIdx.x * blockDim.x + threadIdx.x;
    if (i < 65536) { wvalh[i] = __float2bfloat16(w_val[i]); return; }
    i -= 65536;
    if (i < 65536) { wouth[i] = __float2bfloat16(w_out[i]); return; }
    i -= 65536;
    if (i < 65536) { w1h[i] = __float2bfloat16(w1[i]); return; }
    i -= 65536;
    if (i < 65536) { w2h[i] = __float2bfloat16(w2[i]); return; }
    i -= 65536;
    if (i < 98304) {
        int k = i / 384, n = i % 384;
        wcath[i] = __float2bfloat16(n < 256 ? w_off[k * 256 + n] : w_attn[k * 128 + (n - 256)]);
        return;
    }
    i -= 98304;
    if (i < 384) bcat[i] = (i < 256) ? b_off[i] : b_attn[i - 256];
}

// ---------------- bf16 tensor-core GEMM (BM=128 BN=128 BK=64) ----------------
// mode: 0 fp32 out, 2 bf16 out
__global__ __launch_bounds__(256, 2)
void tgemm(const float* __restrict__ A, const float* __restrict__ A2,
           const __nv_bfloat16* __restrict__ B,
           const float* __restrict__ bias, void* __restrict__ Cv,
           int M, int N, int mode) {
    constexpr int K = 256;
    constexpr int LDA = 72;
    constexpr int LDB = 136;
    __shared__ __align__(16) __nv_bfloat16 As[128 * LDA];
    __shared__ __align__(16) __nv_bfloat16 Bs[64 * LDB];

    int tid = threadIdx.x;
    int lane = tid & 31;
    int wid = tid >> 5;
    int bm = blockIdx.y * 128;
    int bn = blockIdx.x * 128;
    int wm = (wid >> 2) * 64;
    int wn = (wid & 3) * 32;

    float c[4][4][4];
    #pragma unroll
    for (int i = 0; i < 4; i++)
        #pragma unroll
        for (int j = 0; j < 4; j++)
            #pragma unroll
            for (int r = 0; r < 4; r++) c[i][j][r] = 0.f;

    int a_row = lane & 15;
    int a_koff = (lane >> 4) * 8;
    int b_krow = (lane & 7) + ((lane >> 3) & 1) * 8;
    int b_noff = (lane >> 4) * 8;

    for (int k0 = 0; k0 < K; k0 += 64) {
        #pragma unroll
        for (int i = 0; i < 8; i++) {
            int slot = tid + i * 256;
            int row = slot >> 4;
            int k4 = (slot & 15) * 4;
            float4 v = make_float4(0.f, 0.f, 0.f, 0.f);
            if (bm + row < M) {
                v = *reinterpret_cast<const float4*>(A + (size_t)(bm + row) * K + k0 + k4);
                if (A2) {
                    float4 u = *reinterpret_cast<const float4*>(A2 + (size_t)(bm + row) * K + k0 + k4);
                    v.x += u.x; v.y += u.y; v.z += u.z; v.w += u.w;
                }
            }
            __nv_bfloat162 p0 = __floats2bfloat162_rn(v.x, v.y);
            __nv_bfloat162 p1 = __floats2bfloat162_rn(v.z, v.w);
            uint2 st;
            st.x = *reinterpret_cast<uint32_t*>(&p0);
            st.y = *reinterpret_cast<uint32_t*>(&p1);
            *reinterpret_cast<uint2*>(&As[row * LDA + k4]) = st;
        }
        #pragma unroll
        for (int i = 0; i < 4; i++) {
            int slot = tid + i * 256;
            int kk = slot >> 4;
            int n8 = (slot & 15) * 8;
            uint4 v = *reinterpret_cast<const uint4*>(B + (size_t)(k0 + kk) * N + bn + n8);
            *reinterpret_cast<uint4*>(&Bs[kk * LDB + n8]) = v;
        }
        __syncthreads();

        #pragma unroll
        for (int ks = 0; ks < 4; ks++) {
            int kbase = ks * 16;
            uint32_t af[4][4];
            #pragma unroll
            for (int mf = 0; mf < 4; mf++) {
                const __nv_bfloat16* p = &As[(wm + mf * 16 + a_row) * LDA + kbase + a_koff];
                uint32_t addr = (uint32_t)__cvta_generic_to_shared(p);
                asm volatile("ldmatrix.sync.aligned.m8n8.x4.shared.b16 {%0,%1,%2,%3}, [%4];"
                             : "=r"(af[mf][0]), "=r"(af[mf][1]), "=r"(af[mf][2]), "=r"(af[mf][3])
                             : "r"(addr));
            }
            uint32_t bf[4][2];
            #pragma unroll
            for (int n16 = 0; n16 < 2; n16++) {
                const __nv_bfloat16* p = &Bs[(kbase + b_krow) * LDB + wn + n16 * 16 + b_noff];
                uint32_t addr = (uint32_t)__cvta_generic_to_shared(p);
                asm volatile("ldmatrix.sync.aligned.m8n8.x4.trans.shared.b16 {%0,%1,%2,%3}, [%4];"
                             : "=r"(bf[n16 * 2][0]), "=r"(bf[n16 * 2][1]),
                               "=r"(bf[n16 * 2 + 1][0]), "=r"(bf[n16 * 2 + 1][1])
                             : "r"(addr));
            }
            #pragma unroll
            for (int mf = 0; mf < 4; mf++)
                #pragma unroll
                for (int nf = 0; nf < 4; nf++) {
                    asm volatile(
                        "mma.sync.aligned.m16n8k16.row.col.f32.bf16.bf16.f32 "
                        "{%0,%1,%2,%3}, {%4,%5,%6,%7}, {%8,%9}, {%0,%1,%2,%3};"
                        : "+f"(c[mf][nf][0]), "+f"(c[mf][nf][1]),
                          "+f"(c[mf][nf][2]), "+f"(c[mf][nf][3])
                        : "r"(af[mf][0]), "r"(af[mf][1]), "r"(af[mf][2]), "r"(af[mf][3]),
                          "r"(bf[nf][0]), "r"(bf[nf][1]));
                }
        }
        __syncthreads();
    }

    #pragma unroll
    for (int mf = 0; mf < 4; mf++) {
        int row0 = bm + wm + mf * 16 + (lane >> 2);
        #pragma unroll
        for (int nf = 0; nf < 4; nf++) {
            int col = bn + wn + nf * 8 + (lane & 3) * 2;
            float bx = bias[col], by = bias[col + 1];
            float2 v0, v1;
            v0.x = c[mf][nf][0] + bx; v0.y = c[mf][nf][1] + by;
            v1.x = c[mf][nf][2] + bx; v1.y = c[mf][nf][3] + by;
            if (mode == 2) {
                __nv_bfloat16* C = (__nv_bfloat16*)Cv;
                if (row0 < M)
                    *reinterpret_cast<__nv_bfloat162*>(C + (size_t)row0 * N + col) =
                        __floats2bfloat162_rn(v0.x, v0.y);
                if (row0 + 8 < M)
                    *reinterpret_cast<__nv_bfloat162*>(C + (size_t)(row0 + 8) * N + col) =
                        __floats2bfloat162_rn(v1.x, v1.y);
            } else {
                float* C = (float*)Cv;
                if (row0 < M)
                    *reinterpret_cast<float2*>(C + (size_t)row0 * N + col) = v0;
                if (row0 + 8 < M)
                    *reinterpret_cast<float2*>(C + (size_t)(row0 + 8) * N + col) = v1;
            }
        }
    }
}

// ---------------- bf16 GEMM + residual + LayerNorm fused (A bf16, B bf16) ----
__global__ __launch_bounds__(256)
void tgemm_ln(const __nv_bfloat16* __restrict__ A, const __nv_bfloat16* __restrict__ B,
              const float* __restrict__ bias, const float* __restrict__ res,
              const float* __restrict__ gam, const float* __restrict__ bet,
              float* __restrict__ out, int M) {
    constexpr int K = 256;
    constexpr int N = 256;
    constexpr int LDA = 72;
    constexpr int LDB = 264;
    __shared__ __align__(16) __nv_bfloat16 As[64 * LDA];
    __shared__ __align__(16) __nv_bfloat16 Bs[64 * LDB];
    __shared__ float rsum[4][64];
    __shared__ float rsq[4][64];

    int tid = threadIdx.x;
    int lane = tid & 31;
    int wid = tid >> 5;
    int bm = blockIdx.x * 64;
    int wm = (wid >> 2) * 32;
    int wn = (wid & 3) * 64;

    float c[2][8][4];
    #pragma unroll
    for (int i = 0; i < 2; i++)
        #pragma unroll
        for (int j = 0; j < 8; j++)
            #pragma unroll
            for (int r = 0; r < 4; r++) c[i][j][r] = 0.f;

    int a_row = lane & 15;
    int a_koff = (lane >> 4) * 8;
    int b_krow = (lane & 7) + ((lane >> 3) & 1) * 8;
    int b_noff = (lane >> 4) * 8;

    for (int k0 = 0; k0 < K; k0 += 64) {
        #pragma unroll
        for (int i = 0; i < 2; i++) {
            int slot = tid + i * 256;
            int row = slot >> 3;
            int k8 = (slot & 7) * 8;
            uint4 v = make_uint4(0, 0, 0, 0);
            if (bm + row < M)
                v = *reinterpret_cast<const uint4*>(A + (size_t)(bm + row) * K + k0 + k8);
            *reinterpret_cast<uint4*>(&As[row * LDA + k8]) = v;
        }
        #pragma unroll
        for (int i = 0; i < 8; i++) {
            int slot = tid + i * 256;
            int kk = slot >> 5;
            int n8 = (slot & 31) * 8;
            uint4 v = *reinterpret_cast<const uint4*>(B + (size_t)(k0 + kk) * N + n8);
            *reinterpret_cast<uint4*>(&Bs[kk * LDB + n8]) = v;
        }
        __syncthreads();

        #pragma unroll
        for (int ks = 0; ks < 4; ks++) {
            int kbase = ks * 16;
            uint32_t af[2][4];
            #pragma unroll
            for (int mf = 0; mf < 2; mf++) {
                const __nv_bfloat16* p = &As[(wm + mf * 16 + a_row) * LDA + kbase + a_koff];
                uint32_t addr = (uint32_t)__cvta_generic_to_shared(p);
                asm volatile("ldmatrix.sync.aligned.m8n8.x4.shared.b16 {%0,%1,%2,%3}, [%4];"
                             : "=r"(af[mf][0]), "=r"(af[mf][1]), "=r"(af[mf][2]), "=r"(af[mf][3])
                             : "r"(addr));
            }
            uint32_t bf[8][2];
            #pragma unroll
            for (int n16 = 0; n16 < 4; n16++) {
                const __nv_bfloat16* p = &Bs[(kbase + b_krow) * LDB + wn + n16 * 16 + b_noff];
                uint32_t addr = (uint32_t)__cvta_generic_to_shared(p);
                asm volatile("ldmatrix.sync.aligned.m8n8.x4.trans.shared.b16 {%0,%1,%2,%3}, [%4];"
                             : "=r"(bf[n16 * 2][0]), "=r"(bf[n16 * 2][1]),
                               "=r"(bf[n16 * 2 + 1][0]), "=r"(bf[n16 * 2 + 1][1])
                             : "r"(addr));
            }
            #pragma unroll
            for (int mf = 0; mf < 2; mf++)
                #pragma unroll
                for (int nf = 0; nf < 8; nf++) {
                    asm volatile(
                        "mma.sync.aligned.m16n8k16.row.col.f32.bf16.bf16.f32 "
                        "{%0,%1,%2,%3}, {%4,%5,%6,%7}, {%8,%9}, {%0,%1,%2,%3};"
                        : "+f"(c[mf][nf][0]), "+f"(c[mf][nf][1]),
                          "+f"(c[mf][nf][2]), "+f"(c[mf][nf][3])
                        : "r"(af[mf][0]), "r"(af[mf][1]), "r"(af[mf][2]), "r"(af[mf][3]),
                          "r"(bf[nf][0]), "r"(bf[nf][1]));
                }
        }
        __syncthreads();
    }

    float sums[2][2] = {{0.f, 0.f}, {0.f, 0.f}};
    float sqs [2][2] = {{0.f, 0.f}, {0.f, 0.f}};
    #pragma unroll
    for (int mf = 0; mf < 2; mf++) {
        int row0 = bm + wm + mf * 16 + (lane >> 2);
        int row1 = row0 + 8;
        #pragma unroll
        for (int nf = 0; nf < 8; nf++) {
            int col = wn + nf * 8 + (lane & 3) * 2;
            float bx = __ldg(bias + col), by = __ldg(bias + col + 1);
            float2 r0 = make_float2(0.f, 0.f), r1 = make_float2(0.f, 0.f);
            if (row0 < M) r0 = *reinterpret_cast<const float2*>(res + (size_t)row0 * N + col);
            if (row1 < M) r1 = *reinterpret_cast<const float2*>(res + (size_t)row1 * N + col);
            float v0x = c[mf][nf][0] + bx + r0.x;
            float v0y = c[mf][nf][1] + by + r0.y;
            float v1x = c[mf][nf][2] + bx + r1.x;
            float v1y = c[mf][nf][3] + by + r1.y;
            c[mf][nf][0] = v0x; c[mf][nf][1] = v0y;
            c[mf][nf][2] = v1x; c[mf][nf][3] = v1y;
            sums[mf][0] += v0x + v0y;
            sqs [mf][0] += v0x * v0x + v0y * v0y;
            sums[mf][1] += v1x + v1y;
            sqs [mf][1] += v1x * v1x + v1y * v1y;
        }
    }
    #pragma unroll
    for (int o = 1; o <= 2; o <<= 1) {
        #pragma unroll
        for (int mf = 0; mf < 2; mf++)
            #pragma unroll
            for (int hf = 0; hf < 2; hf++) {
                sums[mf][hf] += __shfl_xor_sync(0xffffffffu, sums[mf][hf], o);
                sqs [mf][hf] += __shfl_xor_sync(0xffffffffu, sqs [mf][hf], o);
            }
    }
    if ((lane & 3) == 0) {
        #pragma unroll
        for (int mf = 0; mf < 2; mf++)
            #pragma unroll
            for (int hf = 0; hf < 2; hf++) {
                int rl = wm + mf * 16 + (lane >> 2) + 8 * hf;
                rsum[wid & 3][rl] = sums[mf][hf];
                rsq [wid & 3][rl] = sqs [mf][hf];
            }
    }
    __syncthreads();

    #pragma unroll
    for (int mf = 0; mf < 2; mf++) {
        int rl0 = wm + mf * 16 + (lane >> 2);
        int rl1 = rl0 + 8;
        float s0 = rsum[0][rl0] + rsum[1][rl0] + rsum[2][rl0] + rsum[3][rl0];
        float q0 = rsq [0][rl0] + rsq [1][rl0] + rsq [2][rl0] + rsq [3][rl0];
        float s1 = rsum[0][rl1] + rsum[1][rl1] + rsum[2][rl1] + rsum[3][rl1];
        float q1 = rsq [0][rl1] + rsq [1][rl1] + rsq [2][rl1] + rsq [3][rl1];
        float m0 = s0 * (1.f / 256.f);
        float m1 = s1 * (1.f / 256.f);
        float rs0 = rsqrtf(fmaxf(q0 * (1.f / 256.f) - m0 * m0, 0.f) + 1e-5f);
        float rs1 = rsqrtf(fmaxf(q1 * (1.f / 256.f) - m1 * m1, 0.f) + 1e-5f);
        int row0 = bm + rl0;
        int row1 = bm + rl1;
        #pragma unroll
        for (int nf = 0; nf < 8; nf++) {
            int col = wn + nf * 8 + (lane & 3) * 2;
            float gx = __ldg(gam + col), gy = __ldg(gam + col + 1);
            float bx = __ldg(bet + col), by = __ldg(bet + col + 1);
            if (row0 < M) {
                float2 o0;
                o0.x = (c[mf][nf][0] - m0) * rs0 * gx + bx;
                o0.y = (c[mf][nf][1] - m0) * rs0 * gy + by;
                *reinterpret_cast<float2*>(out + (size_t)row0 * N + col) = o0;
            }
            if (row1 < M) {
                float2 o1;
                o1.x = (c[mf][nf][2] - m1) * rs1 * gx + bx;
                o1.y = (c[mf][nf][3] - m1) * rs1 * gy + by;
                *reinterpret_cast<float2*>(out + (size_t)row1 * N + col) = o1;
            }
        }
    }
}

// ---------------- fused FFN: out = LN(x + relu(x@W1+b1)@W2+b2) ----------------
__global__ __launch_bounds__(256)
void tgemm_ffn(const float* __restrict__ X,
               const __nv_bfloat16* __restrict__ W1, const float* __restrict__ b1,
               const __nv_bfloat16* __restrict__ W2, const float* __restrict__ b2,
               const float* __restrict__ gam, const float* __restrict__ bet,
               float* __restrict__ out, int M) {
    constexpr int K = 256;
    constexpr int N = 256;
    constexpr int LDA = 72;
    constexpr int LDB = 264;
    constexpr int LDH = 264;
    __shared__ __align__(16) __nv_bfloat16 As[64 * LDA];
    __shared__ __align__(16) __nv_bfloat16 Bs[64 * LDB];
    __shared__ __align__(16) __nv_bfloat16 Hs[64 * LDH];
    __shared__ float rsum[4][64];
    __shared__ float rsq[4][64];

    int tid = threadIdx.x;
    int lane = tid & 31;
    int wid = tid >> 5;
    int bm = blockIdx.x * 64;
    int wm = (wid >> 2) * 32;
    int wn = (wid & 3) * 64;

    int a_row = lane & 15;
    int a_koff = (lane >> 4) * 8;
    int b_krow = (lane & 7) + ((lane >> 3) & 1) * 8;
    int b_noff = (lane >> 4) * 8;

    float c[2][8][4];

    #pragma unroll
    for (int i = 0; i < 2; i++)
        #pragma unroll
        for (int j = 0; j < 8; j++)
            #pragma unroll
            for (int r = 0; r < 4; r++) c[i][j][r] = 0.f;

    for (int k0 = 0; k0 < K; k0 += 64) {
        #pragma unroll
        for (int i = 0; i < 4; i++) {
            int slot = tid + i * 256;
            int row = slot >> 4;
            int k4 = (slot & 15) * 4;
            float4 v = make_float4(0.f, 0.f, 0.f, 0.f);
            if (bm + row < M)
                v = *reinterpret_cast<const float4*>(X + (size_t)(bm + row) * K + k0 + k4);
            __nv_bfloat162 p0 = __floats2bfloat162_rn(v.x, v.y);
            __nv_bfloat162 p1 = __floats2bfloat162_rn(v.z, v.w);
            uint2 st;
            st.x = *reinterpret_cast<uint32_t*>(&p0);
            st.y = *reinterpret_cast<uint32_t*>(&p1);
            *reinterpret_cast<uint2*>(&As[row * LDA + k4]) = st;
        }
        #pragma unroll
        for (int i = 0; i < 8; i++) {
            int slot = tid + i * 256;
            int kk = slot >> 5;
            int n8 = (slot & 31) * 8;
            uint4 v = *reinterpret_cast<const uint4*>(W1 + (size_t)(k0 + kk) * N + n8);
            *reinterpret_cast<uint4*>(&Bs[kk * LDB + n8]) = v;
        }
        __syncthreads();

        #pragma unroll
        for (int ks = 0; ks < 4; ks++) {
            int kbase = ks * 16;
            uint32_t af[2][4];
            #pragma unroll
            for (int mf = 0; mf < 2; mf++) {
                const __nv_bfloat16* p = &As[(wm + mf * 16 + a_row) * LDA + kbase + a_koff];
                uint32_t addr = (uint32_t)__cvta_generic_to_shared(p);
                asm volatile("ldmatrix.sync.aligned.m8n8.x4.shared.b16 {%0,%1,%2,%3}, [%4];"
                             : "=r"(af[mf][0]), "=r"(af[mf][1]), "=r"(af[mf][2]), "=r"(af[mf][3])
                             : "r"(addr));
            }
            uint32_t bf[8][2];
            #pragma unroll
            for (int n16 = 0; n16 < 4; n16++) {
                const __nv_bfloat16* p = &Bs[(kbase + b_krow) * LDB + wn + n16 * 16 + b_noff];
                uint32_t addr = (uint32_t)__cvta_generic_to_shared(p);
                asm volatile("ldmatrix.sync.aligned.m8n8.x4.trans.shared.b16 {%0,%1,%2,%3}, [%4];"
                             : "=r"(bf[n16 * 2][0]), "=r"(bf[n16 * 2][1]),
                               "=r"(bf[n16 * 2 + 1][0]), "=r"(bf[n16 * 2 + 1][1])
                             : "r"(addr));
            }
            #pragma unroll
            for (int mf = 0; mf < 2; mf++)
                #pragma unroll
                for (int nf = 0; nf < 8; nf++) {
                    asm volatile(
                        "mma.sync.aligned.m16n8k16.row.col.f32.bf16.bf16.f32 "
                        "{%0,%1,%2,%3}, {%4,%5,%6,%7}, {%8,%9}, {%0,%1,%2,%3};"
                        : "+f"(c[mf][nf][0]), "+f"(c[mf][nf][1]),
                          "+f"(c[mf][nf][2]), "+f"(c[mf][nf][3])
                        : "r"(af[mf][0]), "r"(af[mf][1]), "r"(af[mf][2]), "r"(af[mf][3]),
                          "r"(bf[nf][0]), "r"(bf[nf][1]));
                }
        }
        __syncthreads();
    }

    #pragma unroll
    for (int mf = 0; mf < 2; mf++) {
        int rl0 = wm + mf * 16 + (lane >> 2);
        int rl1 = rl0 + 8;
        #pragma unroll
        for (int nf = 0; nf < 8; nf++) {
            int col = wn + nf * 8 + (lane & 3) * 2;
            float bx = __ldg(b1 + col), by = __ldg(b1 + col + 1);
            float h0x = fmaxf(c[mf][nf][0] + bx, 0.f);
            float h0y = fmaxf(c[mf][nf][1] + by, 0.f);
            float h1x = fmaxf(c[mf][nf][2] + bx, 0.f);
            float h1y = fmaxf(c[mf][nf][3] + by, 0.f);
            __nv_bfloat162 p0 = __floats2bfloat162_rn(h0x, h0y);
            __nv_bfloat162 p1 = __floats2bfloat162_rn(h1x, h1y);
            *reinterpret_cast<__nv_bfloat162*>(&Hs[rl0 * LDH + col]) = p0;
            *reinterpret_cast<__nv_bfloat162*>(&Hs[rl1 * LDH + col]) = p1;
        }
    }
    __syncthreads();

    #pragma unroll
    for (int i = 0; i < 2; i++)
        #pragma unroll
        for (int j = 0; j < 8; j++)
            #pragma unroll
            for (int r = 0; r < 4; r++) c[i][j][r] = 0.f;

    for (int k0 = 0; k0 < K; k0 += 64) {
        #pragma unroll
        for (int i = 0; i < 8; i++) {
            int slot = tid + i * 256;
            int kk = slot >> 5;
            int n8 = (slot & 31) * 8;
            uint4 v = *reinterpret_cast<const uint4*>(W2 + (size_t)(k0 + kk) * N + n8);
            *reinterpret_cast<uint4*>(&Bs[kk * LDB + n8]) = v;
        }
        __syncthreads();

        #pragma unroll
        for (int ks = 0; ks < 4; ks++) {
            int kbase = k0 + ks * 16;
            uint32_t af[2][4];
            #pragma unroll
            for (int mf = 0; mf < 2; mf++) {
                const __nv_bfloat16* p = &Hs[(wm + mf * 16 + a_row) * LDH + kbase + a_koff];
                uint32_t addr = (uint32_t)__cvta_generic_to_shared(p);
                asm volatile("ldmatrix.sync.aligned.m8n8.x4.shared.b16 {%0,%1,%2,%3}, [%4];"
                             : "=r"(af[mf][0]), "=r"(af[mf][1]), "=r"(af[mf][2]), "=r"(af[mf][3])
                             : "r"(addr));
            }
            uint32_t bf[8][2];
            #pragma unroll
            for (int n16 = 0; n16 < 4; n16++) {
                const __nv_bfloat16* p = &Bs[((ks * 16) + b_krow) * LDB + wn + n16 * 16 + b_noff];
                uint32_t addr = (uint32_t)__cvta_generic_to_shared(p);
                asm volatile("ldmatrix.sync.aligned.m8n8.x4.trans.shared.b16 {%0,%1,%2,%3}, [%4];"
                             : "=r"(bf[n16 * 2][0]), "=r"(bf[n16 * 2][1]),
                               "=r"(bf[n16 * 2 + 1][0]), "=r"(bf[n16 * 2 + 1][1])
                             : "r"(addr));
            }
            #pragma unroll
            for (int mf = 0; mf < 2; mf++)
                #pragma unroll
                for (int nf = 0; nf < 8; nf++) {
                    asm volatile(
                        "mma.sync.aligned.m16n8k16.row.col.f32.bf16.bf16.f32 "
                        "{%0,%1,%2,%3}, {%4,%5,%6,%7}, {%8,%9}, {%0,%1,%2,%3};"
                        : "+f"(c[mf][nf][0]), "+f"(c[mf][nf][1]),
                          "+f"(c[mf][nf][2]), "+f"(c[mf][nf][3])
                        : "r"(af[mf][0]), "r"(af[mf][1]), "r"(af[mf][2]), "r"(af[mf][3]),
                          "r"(bf[nf][0]), "r"(bf[nf][1]));
                }
        }
        __syncthreads();
    }

    float sums[2][2] = {{0.f, 0.f}, {0.f, 0.f}};
    float sqs [2][2] = {{0.f, 0.f}, {0.f, 0.f}};
    #pragma unroll
    for (int mf = 0; mf < 2; mf++) {
        int row0 = bm + wm + mf * 16 + (lane >> 2);
        int row1 = row0 + 8;
        #pragma unroll
        for (int nf = 0; nf < 8; nf++) {
            int col = wn + nf * 8 + (lane & 3) * 2;
            float bx = __ldg(b2 + col), by = __ldg(b2 + col + 1);
            float2 r0 = make_float2(0.f, 0.f), r1 = make_float2(0.f, 0.f);
            if (row0 < M) r0 = *reinterpret_cast<const float2*>(X + (size_t)row0 * N + col);
            if (row1 < M) r1 = *reinterpret_cast<const float2*>(X + (size_t)row1 * N + col);
            float v0x = c[mf][nf][0] + bx + r0.x;
            float v0y = c[mf][nf][1] + by + r0.y;
            float v1x = c[mf][nf][2] + bx + r1.x;
            float v1y = c[mf][nf][3] + by + r1.y;
            c[mf][nf][0] = v0x; c[mf][nf][1] = v0y;
            c[mf][nf][2] = v1x; c[mf][nf][3] = v1y;
            sums[mf][0] += v0x + v0y;
            sqs [mf][0] += v0x * v0x + v0y * v0y;
            sums[mf][1] += v1x + v1y;
            sqs [mf][1] += v1x * v1x + v1y * v1y;
        }
    }
    #pragma unroll
    for (int o = 1; o <= 2; o <<= 1) {
        #pragma unroll
        for (int mf = 0; mf < 2; mf++)
            #pragma unroll
            for (int hf = 0; hf < 2; hf++) {
                sums[mf][hf] += __shfl_xor_sync(0xffffffffu, sums[mf][hf], o);
                sqs [mf][hf] += __shfl_xor_sync(0xffffffffu, sqs [mf][hf], o);
            }
    }
    if ((lane & 3) == 0) {
        #pragma unroll
        for (int mf = 0; mf < 2; mf++)
            #pragma unroll
            for (int hf = 0; hf < 2; hf++) {
                int rl = wm + mf * 16 + (lane >> 2) + 8 * hf;
                rsum[wid & 3][rl] = sums[mf][hf];
                rsq [wid & 3][rl] = sqs [mf][hf];
            }
    }
    __syncthreads();

    #pragma unroll
    for (int mf = 0; mf < 2; mf++) {
        int rl0 = wm + mf * 16 + (lane >> 2);
        int rl1 = rl0 + 8;
        float s0 = rsum[0][rl0] + rsum[1][rl0] + rsum[2][rl0] + rsum[3][rl0];
        float q0 = rsq [0][rl0] + rsq [1][rl0] + rsq [2][rl0] + rsq [3][rl0];
        float s1 = rsum[0][rl1] + rsum[1][rl1] + rsum[2][rl1] + rsum[3][rl1];
        float q1 = rsq [0][rl1] + rsq [1][rl1] + rsq [2][rl1] + rsq [3][rl1];
        float m0 = s0 * (1.f / 256.f);
        float m1 = s1 * (1.f / 256.f);
        float rs0 = rsqrtf(fmaxf(q0 * (1.f / 256.f) - m0 * m0, 0.f) + 1e-5f);
        float rs1 = rsqrtf(fmaxf(q1 * (1.f / 256.f) - m1 * m1, 0.f) + 1e-5f);
        int row0 = bm + rl0;
        int row1 = bm + rl1;
        #pragma unroll
        for (int nf = 0; nf < 8; nf++) {
            int col = wn + nf * 8 + (lane & 3) * 2;
            float gx = __ldg(gam + col), gy = __ldg(gam + col + 1);
            float bx = __ldg(bet + col), by = __ldg(bet + col + 1);
            if (row0 < M) {
                float2 o0;
                o0.x = (c[mf][nf][0] - m0) * rs0 * gx + bx;
                o0.y = (c[mf][nf][1] - m0) * rs0 * gy + by;
                *reinterpret_cast<float2*>(out + (size_t)row0 * N + col) = o0;
            }
            if (row1 < M) {
                float2 o1;
                o1.x = (c[mf][nf][2] - m1) * rs1 * gx + bx;
                o1.y = (c[mf][nf][3] - m1) * rs1 * gy + by;
                *reinterpret_cast<float2*>(out + (size_t)row1 * N + col) = o1;
            }
        }
    }
}

// ---------------- deformable sampling: 2 queries per CTA ----------
__global__ __launch_bounds__(256)
void sample_kernel(const __nv_bfloat16* __restrict__ valh,
                   const float* __restrict__ refp,
                   const float* __restrict__ ol,
                   const int* __restrict__ shapes,
                   const int* __restrict__ starts,
                   __nv_bfloat16* __restrict__ acc,
                   int nq) {
    __shared__ __align__(16) int2 pw_s[1024];

    int lq0 = blockIdx.x * 2;
    int tid = threadIdx.x;
    int h = tid >> 5;
    int lane = tid & 31;
    const unsigned FULL = 0xffffffffu;

    {
        int lq = lq0 + (tid >> 7);
        int jh = (tid >> 4) & 7;
        int p = tid & 15;
        int l = p >> 2;
        bool qvalid = lq < nq;
        size_t olbase = (size_t)min(lq, nq - 1) * 384;

        float myl = __ldg(ol + olbase + 256 + jh * 16 + p);
        float mx = myl;
        #pragma unroll
        for (int o = 1; o <= 8; o <<= 1) mx = fmaxf(mx, __shfl_xor_sync(FULL, mx, o));
        float e = __expf(myl - mx);
        float s = e;
        #pragma unroll
        for (int o = 1; o <= 8; o <<= 1) s += __shfl_xor_sync(FULL, s, o);
        float aw = e / s;

        int Hl = __ldg(&shapes[l * 2 + 0]);
        int Wl = __ldg(&shapes[l * 2 + 1]);
        int st = __ldg(&starts[l]);
        float fW = (float)Wl, fH = (float)Hl;

        float rx = __ldg(&refp[(size_t)min(lq, nq - 1) * 8 + l * 2 + 0]);
        float ry = __ldg(&refp[(size_t)min(lq, nq - 1) * 8 + l * 2 + 1]);
        float2 oxy = __ldg(reinterpret_cast<const float2*>(ol + olbase + jh * 32 + p * 2));

        float x = rx * fW + oxy.x - 0.5f;
        float y = ry * fH + oxy.y - 0.5f;
        float x0f = floorf(x), y0f = floorf(y);
        float fx = x - x0f, fy = y - y0f;
        int x0 = (int)x0f, y0 = (int)y0f;

        float wx1 = fx * aw, wx0 = aw - wx1;
        float w00 = wx0 * (1.f - fy), w01 = wx1 * (1.f - fy);
        float w10 = wx0 * fy,         w11 = wx1 * fy;

        bool vx0 = (unsigned)x0 < (unsigned)Wl;
        bool vx1 = (unsigned)(x0 + 1) < (unsigned)Wl;
        bool vy0 = (unsigned)y0 < (unsigned)Hl;
        bool vy1 = (unsigned)(y0 + 1) < (unsigned)Hl;
        if (!(vx0 && vy0) || !qvalid) w00 = 0.f;
        if (!(vx1 && vy0) || !qvalid) w01 = 0.f;
        if (!(vx0 && vy1) || !qvalid) w10 = 0.f;
        if (!(vx1 && vy1) || !qvalid) w11 = 0.f;

        int xc0 = min(max(x0, 0), Wl - 1);
        int xc1 = min(max(x0 + 1, 0), Wl - 1);
        int yc0 = min(max(y0, 0), Hl - 1);
        int yc1 = min(max(y0 + 1, 0), Hl - 1);
        int base = st * 512 + jh * 64;
        int r0 = yc0 * Wl, r1 = yc1 * Wl;

        int4 e0, e1;
        e0.x = base + (r0 + xc0) * 512; e0.y = __float_as_int(w00);
        e0.z = base + (r0 + xc1) * 512; e0.w = __float_as_int(w01);
        e1.x = base + (r1 + xc0) * 512; e1.y = __float_as_int(w10);
        e1.z = base + (r1 + xc1) * 512; e1.w = __float_as_int(w11);
        int4* dst = reinterpret_cast<int4*>(&pw_s[tid * 4]);
        dst[0] = e0;
        dst[1] = e1;
    }
    __syncthreads();

    {
        int cor = lane >> 2;
        int ch = lane & 3;
        const char* vbase = reinterpret_cast<const char*>(valh) + 16 * ch;
        #pragma unroll
        for (int q = 0; q < 2; q++) {
            int lq = lq0 + q;
            if (lq >= nq) break;
            const int2* pw = pw_s + q * 512 + h * 64;
            int2 qr[8];
            #pragma unroll
            for (int i = 0; i < 8; i++) qr[i] = pw[i * 8 + cor];
            float a[8];
            #pragma unroll
            for (int i = 0; i < 8; i++) a[i] = 0.f;
            #pragma unroll
            for (int i = 0; i < 8; i++) {
                float w = __int_as_float(qr[i].y);
                uint4 v = *reinterpret_cast<const uint4*>(vbase + qr[i].x);
                float2 f0 = __bfloat1622float2(*reinterpret_cast<__nv_bfloat162*>(&v.x));
                float2 f1 = __bfloat1622float2(*reinterpret_cast<__nv_bfloat162*>(&v.y));
                float2 f2 = __bfloat1622float2(*reinterpret_cast<__nv_bfloat162*>(&v.z));
                float2 f3 = __bfloat1622float2(*reinterpret_cast<__nv_bfloat162*>(&v.w));
                a[0] += w * f0.x; a[1] += w * f0.y;
                a[2] += w * f1.x; a[3] += w * f1.y;
                a[4] += w * f2.x; a[5] += w * f2.y;
                a[6] += w * f3.x; a[7] += w * f3.y;
            }
            #pragma unroll
            for (int o = 4; o <= 16; o <<= 1)
                #pragma unroll
                for (int i = 0; i < 8; i++)
                    a[i] += __shfl_xor_sync(FULL, a[i], o);
            if (lane < 4) {
                __nv_bfloat162 b0 = __floats2bfloat162_rn(a[0], a[1]);
                __nv_bfloat162 b1 = __floats2bfloat162_rn(a[2], a[3]);
                __nv_bfloat162 b2 = __floats2bfloat162_rn(a[4], a[5]);
                __nv_bfloat162 b3 = __floats2bfloat162_rn(a[6], a[7]);
                uint4 pk;
                pk.x = *reinterpret_cast<uint32_t*>(&b0);
                pk.y = *reinterpret_cast<uint32_t*>(&b1);
                pk.z = *reinterpret_cast<uint32_t*>(&b2);
                pk.w = *reinterpret_cast<uint32_t*>(&b3);
                *reinterpret_cast<uint4*>(acc + (size_t)lq * 256 + h * 32 + 8 * ch) = pk;
            }
        }
    }
}

// ---------------- host ----------------
extern "C" void kernel_launch(void* const* d_in, const int* in_sizes, int n_in,
                              void* d_out, int out_size) {
    const float* query = (const float*)d_in[0];
    const float* refp  = (const float*)d_in[1];
    const float* pos   = (const float*)d_in[2];
    const int*   shp   = (const int*)d_in[3];
    const int*   sti   = (const int*)d_in[4];
    const float* w_off = (const float*)d_in[5];
    const float* b_off = (const float*)d_in[6];
    const float* w_attn= (const float*)d_in[7];
    const float* b_attn= (const float*)d_in[8];
    const float* w_val = (const float*)d_in[9];
    const float* b_val = (const float*)d_in[10];
    const float* w_out = (const float*)d_in[11];
    const float* b_out = (const float*)d_in[12];
    const float* g1    = (const float*)d_in[13];
    const float* be1   = (const float*)d_in[14];
    const float* w1    = (const float*)d_in[15];
    const float* b1    = (const float*)d_in[16];
    const float* w2    = (const float*)d_in[17];
    const float* b2    = (const float*)d_in[18];
    const float* g2    = (const float*)d_in[19];
    const float* be2   = (const float*)d_in[20];
    float* out = (float*)d_out;

    float *ol, *x, *bcat;
    __nv_bfloat16 *valh, *acch, *wvalh, *wouth, *w1h, *w2h, *wcath;
    cudaGetSymbolAddress((void**)&valh,  g_valh);
    cudaGetSymbolAddress((void**)&acch,  g_acch);
    cudaGetSymbolAddress((void**)&ol,    g_ol);
    cudaGetSymbolAddress((void**)&x,     g_x);
    cudaGetSymbolAddress((void**)&wvalh, g_wvalh);
    cudaGetSymbolAddress((void**)&wouth, g_wouth);
    cudaGetSymbolAddress((void**)&w1h,   g_w1h);
    cudaGetSymbolAddress((void**)&w2h,   g_w2h);
    cudaGetSymbolAddress((void**)&wcath, g_wcath);
    cudaGetSymbolAddress((void**)&bcat,  g_bcat);

    const int M = LQ;
    const int M0 = 21504;                  // multiple of 64 and 2
    const int M1 = M - M0;                 // 21550
    dim3 grid_n256(2, (M + 127) / 128);
    dim3 grid_n384(3, (M + 127) / 128);

    cudaStream_t s1;
    cudaStreamCreateWithFlags(&s1, cudaStreamNonBlocking);
    cudaEvent_t e0, e1, e2;
    cudaEventCreateWithFlags(&e0, cudaEventDisableTiming);
    cudaEventCreateWithFlags(&e1, cudaEventDisableTiming);
    cudaEventCreateWithFlags(&e2, cudaEventDisableTiming);

    pack_all<<<(360832 + 255) / 256, 256>>>(w_val, w_out, w1, w2, w_off, w_attn,
                                            b_off, b_attn,
                                            wvalh, wouth, w1h, w2h, wcath, bcat);

    cudaEventRecord(e0, 0);
    cudaStreamWaitEvent(s1, e0, 0);
    // value projection on s1; merged offsets+logits on default stream
    tgemm<<<grid_n256, 256, 0, s1>>>(query, nullptr, wvalh, b_val, valh, M, 256, 2);
    tgemm<<<grid_n384, 256>>>(query, pos, wcath, bcat, ol, M, 384, 0);

    // cross-sync: both streams need valh + ol before sampling
    cudaEventRecord(e2, 0);
    cudaEventRecord(e1, s1);
    cudaStreamWaitEvent(0, e1, 0);
    cudaStreamWaitEvent(s1, e2, 0);

    // pipeline half 0 on default, half 1 on s1
    sample_kernel<<<M0 / 2, 256>>>(valh, refp, ol, shp, sti, acch, M0);
    sample_kernel<<<(M1 + 1) / 2, 256, 0, s1>>>(valh, refp + (size_t)M0 * 8,
                                                ol + (size_t)M0 * 384, shp, sti,
                                                acch + (size_t)M0 * 256, M1);

    tgemm_ln<<<M0 / 64, 256>>>(acch, wouth, b_out, query, g1, be1, x, M0);
    tgemm_ln<<<(M1 + 63) / 64, 256, 0, s1>>>(acch + (size_t)M0 * 256, wouth, b_out,
                                             query + (size_t)M0 * 256, g1, be1,
                                             x + (size_t)M0 * 256, M1);

    tgemm_ffn<<<M0 / 64, 256>>>(x, w1h, b1, w2h, b2, g2, be2, out, M0);
    tgemm_ffn<<<(M1 + 63) / 64, 256, 0, s1>>>(x + (size_t)M0 * 256, w1h, b1, w2h, b2,
                                              g2, be2, out + (size_t)M0 * 256, M1);

    // join: default stream must wait for s1's half before kernel_launch returns work
    cudaEventRecord(e1, s1);
    cudaStreamWaitEvent(0, e1, 0);
}